// round 1
// baseline (speedup 1.0000x reference)
#include <cuda_runtime.h>
#include <cstdint>

// ---------------------------------------------------------------------------
// Problem constants (fixed by setup_inputs)
// ---------------------------------------------------------------------------
#define HEADS 8
#define HD    32
#define DIM   256
#define KVD   512
#define HB    128
#define WB    128
#define HT    64
#define WT    64
#define NPIX  16384         // Hb*Wb per batch
#define NWIN  4096          // Ht*Wt per batch
#define BATCH 4
#define ATT_SCALE 0.17677669529663687f   // 32^-0.5

// ---------------------------------------------------------------------------
// Scratch (device globals; no runtime allocation allowed)
// ---------------------------------------------------------------------------
__device__ float g_Q [BATCH * NPIX * DIM];        // 67 MB : per-pixel q projection
__device__ float g_KV[BATCH * NWIN * KVD];        // 33 MB : k (0..255) | v (256..511)
__device__ float g_P [BATCH * NPIX * DIM];        // 67 MB : pre-proj output
__device__ float g_E [BATCH * NWIN * HEADS * 16]; // 8.4 MB: exp(logit) per entry
__device__ float g_S [BATCH * HEADS * NPIX];      // 2 MB  : per-pixel exp-sums

// ---------------------------------------------------------------------------
// SGEMM: C[m,n] = sum_k A[m,k] * B[n,k]  (+ bias[n])
// A: MxK row-major, B: NxK row-major. M%128==0, N%128==0, K%16==0.
// 128x128 block tile, BK=16, 256 threads, 8x8 per-thread register tile.
// ---------------------------------------------------------------------------
#define BM 128
#define BN 128
#define BK 16

__global__ __launch_bounds__(256)
void sgemm_abt(const float* __restrict__ A, const float* __restrict__ B,
               const float* __restrict__ bias, float* __restrict__ C,
               int M, int N, int K)
{
    __shared__ float As[BK][BM];
    __shared__ float Bs[BK][BN];

    const int bm  = blockIdx.y * BM;
    const int bn  = blockIdx.x * BN;
    const int tid = threadIdx.x;
    const int tx  = tid & 15;       // 0..15 -> 8 cols each
    const int ty  = tid >> 4;       // 0..15 -> 8 rows each

    const int lrow = tid >> 2;      // 0..63
    const int lk4  = (tid & 3) * 4; // 0,4,8,12

    float acc[8][8];
#pragma unroll
    for (int i = 0; i < 8; i++)
#pragma unroll
        for (int j = 0; j < 8; j++) acc[i][j] = 0.f;

    for (int k0 = 0; k0 < K; k0 += BK) {
#pragma unroll
        for (int r = 0; r < 2; r++) {
            const int row = lrow + r * 64;
            float4 va = *(const float4*)(A + (size_t)(bm + row) * K + k0 + lk4);
            As[lk4 + 0][row] = va.x;
            As[lk4 + 1][row] = va.y;
            As[lk4 + 2][row] = va.z;
            As[lk4 + 3][row] = va.w;
            float4 vb = *(const float4*)(B + (size_t)(bn + row) * K + k0 + lk4);
            Bs[lk4 + 0][row] = vb.x;
            Bs[lk4 + 1][row] = vb.y;
            Bs[lk4 + 2][row] = vb.z;
            Bs[lk4 + 3][row] = vb.w;
        }
        __syncthreads();

#pragma unroll
        for (int k = 0; k < BK; k++) {
            float a[8], b[8];
            *(float4*)&a[0] = *(const float4*)&As[k][ty * 8];
            *(float4*)&a[4] = *(const float4*)&As[k][ty * 8 + 4];
            *(float4*)&b[0] = *(const float4*)&Bs[k][tx * 8];
            *(float4*)&b[4] = *(const float4*)&Bs[k][tx * 8 + 4];
#pragma unroll
            for (int i = 0; i < 8; i++)
#pragma unroll
                for (int j = 0; j < 8; j++)
                    acc[i][j] = fmaf(a[i], b[j], acc[i][j]);
        }
        __syncthreads();
    }

#pragma unroll
    for (int i = 0; i < 8; i++) {
        const int row = bm + ty * 8 + i;
        float* cp = C + (size_t)row * N + bn + tx * 8;
        float4 o0 = make_float4(acc[i][0], acc[i][1], acc[i][2], acc[i][3]);
        float4 o1 = make_float4(acc[i][4], acc[i][5], acc[i][6], acc[i][7]);
        if (bias) {
            const float* bp = bias + bn + tx * 8;
            o0.x += bp[0]; o0.y += bp[1]; o0.z += bp[2]; o0.w += bp[3];
            o1.x += bp[4]; o1.y += bp[5]; o1.z += bp[6]; o1.w += bp[7];
        }
        *(float4*)cp       = o0;
        *(float4*)(cp + 4) = o1;
    }
}

// ---------------------------------------------------------------------------
// Covering-window enumeration helper.
// Fine pixel row r is patch element i of window row ty iff 2*ty + i == r+1,
// i in [0,4), ty in [0,64). At most 2 candidates per axis.
// ---------------------------------------------------------------------------
__device__ __forceinline__ int covers(int r, int lim, int tys[2], int iis[2])
{
    const int th = (r + 1) >> 1;
    const int ih = (r + 1) & 1;
    int n = 0;
    if (th < lim) { tys[n] = th;     iis[n] = ih;     n++; }
    if (th >= 1)  { tys[n] = th - 1; iis[n] = ih + 2; n++; }
    return n;
}

// ---------------------------------------------------------------------------
// Attention phase 1: per fine pixel, per head:
//   logits for the <=4 covering (window,patch) entries; write exp(logit)
//   to g_E and the per-pixel sum to g_S.
// Block = 256 threads (warp w handles head w); grid = BATCH*NPIX.
// ---------------------------------------------------------------------------
__global__ __launch_bounds__(256)
void attn_phase1(const float* __restrict__ Q, const float* __restrict__ KV,
                 const float* __restrict__ rel_init,
                 const float* __restrict__ rel_bias)
{
    const int pix  = blockIdx.x;         // b*NPIX + r*WB + c
    const int b    = pix >> 14;
    const int rc   = pix & (NPIX - 1);
    const int r    = rc >> 7;
    const int c    = rc & (WB - 1);
    const int t    = threadIdx.x;        // h*32 + d
    const int h    = t >> 5;
    const int lane = t & 31;

    const float q = Q[(size_t)pix * DIM + t];

    int tys[2], iis[2], txs[2], jjs[2];
    const int nty = covers(r, HT, tys, iis);
    const int ntx = covers(c, WT, txs, jjs);

    float ssum = 0.f;
#pragma unroll
    for (int a = 0; a < 2; a++) {
        if (a >= nty) break;
#pragma unroll
        for (int e = 0; e < 2; e++) {
            if (e >= ntx) break;
            const int w = tys[a] * WT + txs[e];
            const int p = iis[a] * 4 + jjs[e];
            const float* kvp = KV + (size_t)(b * NWIN + w) * KVD;
            float partial = q * kvp[t];
#pragma unroll
            for (int off = 16; off; off >>= 1)
                partial += __shfl_xor_sync(0xffffffffu, partial, off);
            const float logit = partial * ATT_SCALE + rel_init[p] + rel_bias[p];
            const float ex = expf(logit);   // identical on all 32 lanes
            ssum += ex;
            if (lane == 0)
                g_E[((size_t)(b * NWIN + w) * HEADS + h) * 16 + p] = ex;
        }
    }
    if (lane == 0)
        g_S[(size_t)(b * HEADS + h) * NPIX + rc] = ssum;
}

// ---------------------------------------------------------------------------
// Attention phase 2: per fine pixel, apply the reference's (layout-scrambled)
// normalization, weight V, overlap-add (fold) into g_P.
// Reference reshape bug: divisor for (window hw, head h) is the pixel-sum of
// head h2 = hw>>9 at window hw2 = (hw&511)*8 + h (1.0 if that pixel is OOB).
// ---------------------------------------------------------------------------
__global__ __launch_bounds__(256)
void attn_phase2(const float* __restrict__ KV, float* __restrict__ P)
{
    const int pix = blockIdx.x;
    const int b   = pix >> 14;
    const int rc  = pix & (NPIX - 1);
    const int r   = rc >> 7;
    const int c   = rc & (WB - 1);
    const int t   = threadIdx.x;
    const int h   = t >> 5;

    int tys[2], iis[2], txs[2], jjs[2];
    const int nty = covers(r, HT, tys, iis);
    const int ntx = covers(c, WT, txs, jjs);

    float out = 0.f;
#pragma unroll
    for (int a = 0; a < 2; a++) {
        if (a >= nty) break;
#pragma unroll
        for (int e = 0; e < 2; e++) {
            if (e >= ntx) break;
            const int w = tys[a] * WT + txs[e];
            const int p = iis[a] * 4 + jjs[e];

            const float ex = g_E[((size_t)(b * NWIN + w) * HEADS + h) * 16 + p];

            // scrambled divisor lookup (faithful to reference reshape)
            const int h2  = w >> 9;
            const int w2  = ((w & 511) << 3) + h;
            const int r2  = 2 * (w2 >> 6) - 1 + (p >> 2);
            const int c2  = 2 * (w2 & 63) - 1 + (p & 3);
            float denom = 1.f;
            if ((unsigned)r2 < (unsigned)HB && (unsigned)c2 < (unsigned)WB)
                denom = g_S[(size_t)(b * HEADS + h2) * NPIX + r2 * WB + c2];

            const float wgt = ex / denom;
            const float v = KV[(size_t)(b * NWIN + w) * KVD + DIM + t];
            out = fmaf(wgt, v, out);
        }
    }
    P[(size_t)pix * DIM + t] = out;
}

// ---------------------------------------------------------------------------
// Launch
// ---------------------------------------------------------------------------
extern "C" void kernel_launch(void* const* d_in, const int* in_sizes, int n_in,
                              void* d_out, int out_size)
{
    (void)in_sizes; (void)n_in; (void)out_size;
    const float* Xt       = (const float*)d_in[0];
    const float* Xb       = (const float*)d_in[1];
    const float* q_w      = (const float*)d_in[2];
    const float* kv_w     = (const float*)d_in[3];
    const float* proj_w   = (const float*)d_in[4];
    const float* proj_b   = (const float*)d_in[5];
    const float* rel_init = (const float*)d_in[6];
    const float* rel_bias = (const float*)d_in[7];
    float* out = (float*)d_out;

    float *Qb, *KVb, *Pb;
    cudaGetSymbolAddress((void**)&Qb,  g_Q);
    cudaGetSymbolAddress((void**)&KVb, g_KV);
    cudaGetSymbolAddress((void**)&Pb,  g_P);

    const dim3 blk(256);

    // 1) Q = Xb @ q_w^T          (65536 x 256 x 256)
    sgemm_abt<<<dim3(DIM / BN, (BATCH * NPIX) / BM), blk>>>(
        Xb, q_w, nullptr, Qb, BATCH * NPIX, DIM, DIM);

    // 2) KV = Xt @ kv_w^T        (16384 x 512 x 512)
    sgemm_abt<<<dim3(KVD / BN, (BATCH * NWIN) / BM), blk>>>(
        Xt, kv_w, nullptr, KVb, BATCH * NWIN, KVD, KVD);

    // 3) attention numerators + per-pixel sums
    attn_phase1<<<BATCH * NPIX, 256>>>(Qb, KVb, rel_init, rel_bias);

    // 4) scrambled normalization + V weighting + fold
    attn_phase2<<<BATCH * NPIX, 256>>>(KVb, Pb);

    // 5) Out = P @ proj_w^T + proj_b   (65536 x 256 x 256)
    sgemm_abt<<<dim3(DIM / BN, (BATCH * NPIX) / BM), blk>>>(
        Pb, proj_w, proj_b, out, BATCH * NPIX, DIM, DIM);
}

// round 3
// speedup vs baseline: 1.2632x; 1.2632x over previous
#include <cuda_runtime.h>
#include <cstdint>

// ---------------------------------------------------------------------------
// Problem constants (fixed by setup_inputs)
// ---------------------------------------------------------------------------
#define HEADS 8
#define HD    32
#define DIM   256
#define KVD   512
#define HB    128
#define WB    128
#define HT    64
#define WT    64
#define NPIX  16384         // Hb*Wb per batch
#define NWIN  4096          // Ht*Wt per batch
#define BATCH 4
#define ATT_SCALE 0.17677669529663687f   // 32^-0.5

// ---------------------------------------------------------------------------
// Scratch (device globals; no runtime allocation allowed)
// ---------------------------------------------------------------------------
__device__ float g_Q [BATCH * NPIX * DIM];        // 67 MB
__device__ float g_KV[BATCH * NWIN * KVD];        // 33 MB : k | v
__device__ float g_P [BATCH * NPIX * DIM];        // 67 MB
__device__ float g_E [BATCH * NWIN * HEADS * 16]; // 8.4 MB
__device__ float g_S [BATCH * HEADS * NPIX];      // 2 MB

// ---------------------------------------------------------------------------
// SGEMM with packed f32x2 FMAs: C[m,n] = sum_k A[m,k]*B[n,k] (+ bias[n])
// 128x128 tile, BK=16, 256 threads, 8x8 per-thread tile held as 8x4 f32x2.
// ---------------------------------------------------------------------------
#define BM 128
#define BN 128
#define BK 16

__global__ __launch_bounds__(256)
void sgemm_abt(const float* __restrict__ A, const float* __restrict__ B,
               const float* __restrict__ bias, float* __restrict__ C,
               int M, int N, int K)
{
    __shared__ float As[BK][BM];
    __shared__ float Bs[BK][BN];

    const int bm  = blockIdx.y * BM;
    const int bn  = blockIdx.x * BN;
    const int tid = threadIdx.x;
    const int tx  = tid & 15;       // 8 cols each
    const int ty  = tid >> 4;       // 8 rows each

    const int lrow = tid >> 2;      // 0..63
    const int lk4  = (tid & 3) * 4; // 0,4,8,12

    unsigned long long acc2[8][4];  // [i][jp] packs (acc[i][2jp], acc[i][2jp+1])
#pragma unroll
    for (int i = 0; i < 8; i++)
#pragma unroll
        for (int j = 0; j < 4; j++) acc2[i][j] = 0ULL;

    for (int k0 = 0; k0 < K; k0 += BK) {
#pragma unroll
        for (int r = 0; r < 2; r++) {
            const int row = lrow + r * 64;
            float4 va = *(const float4*)(A + (size_t)(bm + row) * K + k0 + lk4);
            As[lk4 + 0][row] = va.x;
            As[lk4 + 1][row] = va.y;
            As[lk4 + 2][row] = va.z;
            As[lk4 + 3][row] = va.w;
            float4 vb = *(const float4*)(B + (size_t)(bn + row) * K + k0 + lk4);
            Bs[lk4 + 0][row] = vb.x;
            Bs[lk4 + 1][row] = vb.y;
            Bs[lk4 + 2][row] = vb.z;
            Bs[lk4 + 3][row] = vb.w;
        }
        __syncthreads();

#pragma unroll
        for (int k = 0; k < BK; k++) {
            float a[8], b[8];
            *(float4*)&a[0] = *(const float4*)&As[k][ty * 8];
            *(float4*)&a[4] = *(const float4*)&As[k][ty * 8 + 4];
            *(float4*)&b[0] = *(const float4*)&Bs[k][tx * 8];
            *(float4*)&b[4] = *(const float4*)&Bs[k][tx * 8 + 4];

            unsigned long long ad[8], bp[4];
#pragma unroll
            for (int i = 0; i < 8; i++)
                asm("mov.b64 %0, {%1, %1};" : "=l"(ad[i]) : "f"(a[i]));
#pragma unroll
            for (int j = 0; j < 4; j++)
                asm("mov.b64 %0, {%1, %2};" : "=l"(bp[j]) : "f"(b[2 * j]), "f"(b[2 * j + 1]));
#pragma unroll
            for (int i = 0; i < 8; i++)
#pragma unroll
                for (int j = 0; j < 4; j++)
                    asm("fma.rn.f32x2 %0, %1, %2, %0;"
                        : "+l"(acc2[i][j]) : "l"(ad[i]), "l"(bp[j]));
        }
        __syncthreads();
    }

#pragma unroll
    for (int i = 0; i < 8; i++) {
        float o[8];
#pragma unroll
        for (int j = 0; j < 4; j++)
            asm("mov.b64 {%0, %1}, %2;" : "=f"(o[2 * j]), "=f"(o[2 * j + 1]) : "l"(acc2[i][j]));
        const int row = bm + ty * 8 + i;
        float* cp = C + (size_t)row * N + bn + tx * 8;
        if (bias) {
            const float* bp = bias + bn + tx * 8;
#pragma unroll
            for (int j = 0; j < 8; j++) o[j] += bp[j];
        }
        *(float4*)cp       = make_float4(o[0], o[1], o[2], o[3]);
        *(float4*)(cp + 4) = make_float4(o[4], o[5], o[6], o[7]);
    }
}

// ---------------------------------------------------------------------------
// Covering-window enumeration: fine pixel row r -> <=2 (window-row, patch-row)
// ---------------------------------------------------------------------------
__device__ __forceinline__ int covers(int r, int lim, int tys[2], int iis[2])
{
    const int th = (r + 1) >> 1;
    const int ih = (r + 1) & 1;
    int n = 0;
    if (th < lim) { tys[n] = th;     iis[n] = ih;     n++; }
    if (th >= 1)  { tys[n] = th - 1; iis[n] = ih + 2; n++; }
    return n;
}

// ---------------------------------------------------------------------------
// Phase 1 (float4, 4 pixels per 256-thread block):
// per (pixel, head): exp(logits) of <=4 covering entries -> g_E, sum -> g_S.
// Sub-block of 64 threads per pixel; thread j covers channels 4j..4j+3;
// head = j>>3 (8 lanes per head).
// ---------------------------------------------------------------------------
__global__ __launch_bounds__(256)
void attn_phase1(const float* __restrict__ Q, const float* __restrict__ KV,
                 const float* __restrict__ rel_init,
                 const float* __restrict__ rel_bias)
{
    const int pix  = blockIdx.x * 4 + (threadIdx.x >> 6);
    const int j    = threadIdx.x & 63;
    const int b    = pix >> 14;
    const int rc   = pix & (NPIX - 1);
    const int r    = rc >> 7;
    const int c    = rc & (WB - 1);
    const int h    = j >> 3;
    const int l8   = j & 7;

    const float4 q = *(const float4*)(Q + (size_t)pix * DIM + j * 4);

    int tys[2], iis[2], txs[2], jjs[2];
    const int nty = covers(r, HT, tys, iis);
    const int ntx = covers(c, WT, txs, jjs);

    float ssum = 0.f;
#pragma unroll
    for (int a = 0; a < 2; a++) {
        if (a >= nty) break;
#pragma unroll
        for (int e = 0; e < 2; e++) {
            if (e >= ntx) break;
            const int w = tys[a] * WT + txs[e];
            const int p = iis[a] * 4 + jjs[e];
            const float4 kk = *(const float4*)(KV + (size_t)(b * NWIN + w) * KVD + j * 4);
            float part = q.x * kk.x + q.y * kk.y + q.z * kk.z + q.w * kk.w;
            part += __shfl_xor_sync(0xffffffffu, part, 4);
            part += __shfl_xor_sync(0xffffffffu, part, 2);
            part += __shfl_xor_sync(0xffffffffu, part, 1);
            const float logit = part * ATT_SCALE + rel_init[p] + rel_bias[p];
            const float ex = expf(logit);   // identical on all 8 lanes of the head
            ssum += ex;
            if (l8 == 0)
                g_E[((size_t)(b * NWIN + w) * HEADS + h) * 16 + p] = ex;
        }
    }
    if (l8 == 0)
        g_S[(size_t)(b * HEADS + h) * NPIX + rc] = ssum;
}

// ---------------------------------------------------------------------------
// Phase 2 (float4, 4 pixels per 256-thread block): scrambled normalization
// (faithful to the reference reshape), V weighting, overlap-add fold -> g_P.
// Divisor for (window w, head h): pixel-sum of head h2 = w>>9 at window
// w2 = (w&511)*8 + h; 1.0 if the mapped pixel is out of bounds.
// ---------------------------------------------------------------------------
__global__ __launch_bounds__(256)
void attn_phase2(const float* __restrict__ KV, float* __restrict__ P)
{
    const int pix = blockIdx.x * 4 + (threadIdx.x >> 6);
    const int j   = threadIdx.x & 63;
    const int b   = pix >> 14;
    const int rc  = pix & (NPIX - 1);
    const int r   = rc >> 7;
    const int c   = rc & (WB - 1);
    const int h   = j >> 3;

    int tys[2], iis[2], txs[2], jjs[2];
    const int nty = covers(r, HT, tys, iis);
    const int ntx = covers(c, WT, txs, jjs);

    float4 out = make_float4(0.f, 0.f, 0.f, 0.f);
#pragma unroll
    for (int a = 0; a < 2; a++) {
        if (a >= nty) break;
#pragma unroll
        for (int e = 0; e < 2; e++) {
            if (e >= ntx) break;
            const int w = tys[a] * WT + txs[e];
            const int p = iis[a] * 4 + jjs[e];

            const float ex = g_E[((size_t)(b * NWIN + w) * HEADS + h) * 16 + p];

            const int h2 = w >> 9;
            const int w2 = ((w & 511) << 3) + h;
            const int r2 = 2 * (w2 >> 6) - 1 + (p >> 2);
            const int c2 = 2 * (w2 & 63) - 1 + (p & 3);
            float denom = 1.f;
            if ((unsigned)r2 < (unsigned)HB && (unsigned)c2 < (unsigned)WB)
                denom = g_S[(size_t)(b * HEADS + h2) * NPIX + r2 * WB + c2];

            const float wgt = ex / denom;
            const float4 v = *(const float4*)(KV + (size_t)(b * NWIN + w) * KVD + DIM + j * 4);
            out.x = fmaf(wgt, v.x, out.x);
            out.y = fmaf(wgt, v.y, out.y);
            out.z = fmaf(wgt, v.z, out.z);
            out.w = fmaf(wgt, v.w, out.w);
        }
    }
    *(float4*)(P + (size_t)pix * DIM + j * 4) = out;
}

// ---------------------------------------------------------------------------
// Launch
// ---------------------------------------------------------------------------
extern "C" void kernel_launch(void* const* d_in, const int* in_sizes, int n_in,
                              void* d_out, int out_size)
{
    (void)in_sizes; (void)n_in; (void)out_size;
    const float* Xt       = (const float*)d_in[0];
    const float* Xb       = (const float*)d_in[1];
    const float* q_w      = (const float*)d_in[2];
    const float* kv_w     = (const float*)d_in[3];
    const float* proj_w   = (const float*)d_in[4];
    const float* proj_b   = (const float*)d_in[5];
    const float* rel_init = (const float*)d_in[6];
    const float* rel_bias = (const float*)d_in[7];
    float* out = (float*)d_out;

    float *Qb, *KVb, *Pb;
    cudaGetSymbolAddress((void**)&Qb,  g_Q);
    cudaGetSymbolAddress((void**)&KVb, g_KV);
    cudaGetSymbolAddress((void**)&Pb,  g_P);

    const dim3 blk(256);

    // 1) Q = Xb @ q_w^T          (65536 x 256 x 256)
    sgemm_abt<<<dim3(DIM / BN, (BATCH * NPIX) / BM), blk>>>(
        Xb, q_w, nullptr, Qb, BATCH * NPIX, DIM, DIM);

    // 2) KV = Xt @ kv_w^T        (16384 x 512 x 512)
    sgemm_abt<<<dim3(KVD / BN, (BATCH * NWIN) / BM), blk>>>(
        Xt, kv_w, nullptr, KVb, BATCH * NWIN, KVD, KVD);

    // 3) attention numerators + per-pixel sums
    attn_phase1<<<(BATCH * NPIX) / 4, 256>>>(Qb, KVb, rel_init, rel_bias);

    // 4) scrambled normalization + V weighting + fold
    attn_phase2<<<(BATCH * NPIX) / 4, 256>>>(KVb, Pb);

    // 5) Out = P @ proj_w^T + proj_b   (65536 x 256 x 256)
    sgemm_abt<<<dim3(DIM / BN, (BATCH * NPIX) / BM), blk>>>(
        Pb, proj_w, proj_b, out, BATCH * NPIX, DIM, DIM);
}

// round 6
// speedup vs baseline: 2.4821x; 1.9649x over previous
#include <cuda_runtime.h>
#include <cuda_bf16.h>
#include <cstdint>

// ---------------------------------------------------------------------------
// Problem constants
// ---------------------------------------------------------------------------
#define HEADS 8
#define DIM   256
#define KVD   512
#define HB    128
#define WB    128
#define HT    64
#define WT    64
#define NPIX  16384
#define NWIN  4096
#define BATCH 4
#define ATT_SCALE 0.17677669529663687f

// ---------------------------------------------------------------------------
// Scratch (device globals)
// ---------------------------------------------------------------------------
__device__ float g_Q [BATCH * NPIX * DIM];
__device__ float g_KV[BATCH * NWIN * KVD];
__device__ float g_E [BATCH * NWIN * HEADS * 16];
__device__ float g_S [BATCH * HEADS * NPIX];

__device__ __nv_bfloat16 g_Xbh[BATCH * NPIX * DIM];
__device__ __nv_bfloat16 g_Xbl[BATCH * NPIX * DIM];
__device__ __nv_bfloat16 g_Xth[BATCH * NWIN * KVD];
__device__ __nv_bfloat16 g_Xtl[BATCH * NWIN * KVD];
__device__ __nv_bfloat16 g_Ph [BATCH * NPIX * DIM];
__device__ __nv_bfloat16 g_Pl [BATCH * NPIX * DIM];
__device__ __nv_bfloat16 g_wqh[DIM * DIM],  g_wql[DIM * DIM];
__device__ __nv_bfloat16 g_wkh[KVD * KVD],  g_wkl[KVD * KVD];
__device__ __nv_bfloat16 g_wph[DIM * DIM],  g_wpl[DIM * DIM];

// ---------------------------------------------------------------------------
// Helpers
// ---------------------------------------------------------------------------
__device__ __forceinline__ uint32_t smem_u32(const void* p) {
    uint32_t a;
    asm("{ .reg .u64 t; cvta.to.shared.u64 t, %1; cvt.u32.u64 %0, t; }"
        : "=r"(a) : "l"(p));
    return a;
}
__device__ __forceinline__ void cpasync16(uint32_t s, const void* g) {
    asm volatile("cp.async.cg.shared.global [%0], [%1], 16;" :: "r"(s), "l"(g));
}
__device__ __forceinline__ void ldm_x4(uint32_t* r, uint32_t addr) {
    asm volatile("ldmatrix.sync.aligned.m8n8.x4.shared.b16 {%0,%1,%2,%3}, [%4];"
                 : "=r"(r[0]), "=r"(r[1]), "=r"(r[2]), "=r"(r[3]) : "r"(addr));
}
__device__ __forceinline__ void mma16816(float* c, const uint32_t* a, const uint32_t* b) {
    asm volatile("mma.sync.aligned.m16n8k16.row.col.f32.bf16.bf16.f32 "
                 "{%0,%1,%2,%3}, {%4,%5,%6,%7}, {%8,%9}, {%0,%1,%2,%3};"
                 : "+f"(c[0]), "+f"(c[1]), "+f"(c[2]), "+f"(c[3])
                 : "r"(a[0]), "r"(a[1]), "r"(a[2]), "r"(a[3]),
                   "r"(b[0]), "r"(b[1]));
}
// swizzled byte offset of (row r, 16B-chunk c) inside a [128 x 64B] tile
__device__ __forceinline__ uint32_t sw_off(int r, int c) {
    return (uint32_t)(r * 64 + ((c ^ ((r >> 1) & 3)) << 4));
}

// ---------------------------------------------------------------------------
// Split fp32 -> (hi, lo) bf16
// ---------------------------------------------------------------------------
__global__ __launch_bounds__(256)
void split_f32(const float* __restrict__ x, __nv_bfloat16* __restrict__ hi,
               __nv_bfloat16* __restrict__ lo, int n4)
{
    int i = blockIdx.x * blockDim.x + threadIdx.x;
    if (i >= n4) return;
    float4 v = ((const float4*)x)[i];
    float xs[4] = {v.x, v.y, v.z, v.w};
    unsigned short hb[4], lb[4];
#pragma unroll
    for (int k = 0; k < 4; k++) {
        __nv_bfloat16 h = __float2bfloat16(xs[k]);
        __nv_bfloat16 l = __float2bfloat16(xs[k] - __bfloat162float(h));
        hb[k] = __bfloat16_as_ushort(h);
        lb[k] = __bfloat16_as_ushort(l);
    }
    ((ushort4*)hi)[i] = make_ushort4(hb[0], hb[1], hb[2], hb[3]);
    ((ushort4*)lo)[i] = make_ushort4(lb[0], lb[1], lb[2], lb[3]);
}

// ---------------------------------------------------------------------------
// HMMA split-bf16 GEMM:  C[m,n] = sum_k A[m,k]*B[n,k] (+bias[n]), fp32 out.
// 3 products per chunk: Ah*Bh + Ah*Bl + Al*Bh. Tile 128x128, BK=32, 8 warps
// (warp tile 32x64), 3-stage cp.async pipeline, XOR-swizzled smem.
// ---------------------------------------------------------------------------
#define TBM 128
#define TBN 128
#define TBK 32
#define TILE_B   8192                 // one [128 x 64B] tile
#define STAGE_B  (4 * TILE_B)        // Ah | Al | Bh | Bl
#define NSTAGE   3
#define GEMM_SMEM (NSTAGE * STAGE_B) // 96 KB

__global__ __launch_bounds__(256, 1)
void gemm_split(const __nv_bfloat16* __restrict__ Ahi,
                const __nv_bfloat16* __restrict__ Alo,
                const __nv_bfloat16* __restrict__ Bhi,
                const __nv_bfloat16* __restrict__ Blo,
                const float* __restrict__ bias,
                float* __restrict__ C,
                int M, int N, int K)
{
    extern __shared__ char dsm[];
    const uint32_t sbase = smem_u32(dsm);

    const int tid  = threadIdx.x;
    const int wid  = tid >> 5;
    const int lane = tid & 31;
    const int wm   = wid & 3;        // 4 warps along M
    const int wn   = wid >> 2;       // 2 warps along N
    const int bm   = blockIdx.y * TBM;
    const int bn   = blockIdx.x * TBN;
    const int KC   = K / TBK;

    float acc[2][8][4];
#pragma unroll
    for (int mi = 0; mi < 2; mi++)
#pragma unroll
        for (int ni = 0; ni < 8; ni++)
#pragma unroll
            for (int q = 0; q < 4; q++) acc[mi][ni][q] = 0.f;

    auto load_chunk = [&](int ch, int stage) {
        const int k0 = ch * TBK;
        const uint32_t st = sbase + stage * STAGE_B;
#pragma unroll
        for (int t2 = 0; t2 < 2; t2++) {
            const int id = tid + t2 * 256;   // 0..511
            const int r  = id >> 2;
            const int c  = id & 3;
            const uint32_t off = sw_off(r, c);
            const size_t ga = (size_t)(bm + r) * K + k0 + c * 8;
            const size_t gb = (size_t)(bn + r) * K + k0 + c * 8;
            cpasync16(st + 0 * TILE_B + off, Ahi + ga);
            cpasync16(st + 1 * TILE_B + off, Alo + ga);
            cpasync16(st + 2 * TILE_B + off, Bhi + gb);
            cpasync16(st + 3 * TILE_B + off, Blo + gb);
        }
        asm volatile("cp.async.commit_group;" ::: "memory");
    };

    // prologue
    load_chunk(0, 0);
    if (KC > 1) load_chunk(1, 1); else asm volatile("cp.async.commit_group;" ::: "memory");
    if (KC > 2) load_chunk(2, 2); else asm volatile("cp.async.commit_group;" ::: "memory");

    for (int ch = 0; ch < KC; ch++) {
        asm volatile("cp.async.wait_group 2;" ::: "memory");
        __syncthreads();

        const uint32_t st = sbase + (ch % NSTAGE) * STAGE_B;
#pragma unroll
        for (int ks = 0; ks < 2; ks++) {
            uint32_t ah[2][4], al[2][4], bh[8][2], bl[8][2];
            // A fragments: rows wm*32 + mi*16 + ..., k chunk ks
#pragma unroll
            for (int mi = 0; mi < 2; mi++) {
                const int r = wm * 32 + mi * 16 + ((lane >> 3) & 1) * 8 + (lane & 7);
                const int c = ks * 2 + (lane >> 4);
                const uint32_t off = sw_off(r, c);
                ldm_x4(ah[mi], st + 0 * TILE_B + off);
                ldm_x4(al[mi], st + 1 * TILE_B + off);
            }
            // B fragments: 4 x4-loads cover 8 n8-tiles
#pragma unroll
            for (int g = 0; g < 4; g++) {
                const int r = wn * 64 + g * 16 + ((lane >> 4) & 1) * 8 + (lane & 7);
                const int c = ks * 2 + ((lane >> 3) & 1);
                const uint32_t off = sw_off(r, c);
                uint32_t th[4], tl[4];
                ldm_x4(th, st + 2 * TILE_B + off);
                ldm_x4(tl, st + 3 * TILE_B + off);
                bh[2 * g][0] = th[0]; bh[2 * g][1] = th[1];
                bh[2 * g + 1][0] = th[2]; bh[2 * g + 1][1] = th[3];
                bl[2 * g][0] = tl[0]; bl[2 * g][1] = tl[1];
                bl[2 * g + 1][0] = tl[2]; bl[2 * g + 1][1] = tl[3];
            }
#pragma unroll
            for (int mi = 0; mi < 2; mi++)
#pragma unroll
                for (int ni = 0; ni < 8; ni++) {
                    mma16816(acc[mi][ni], ah[mi], bh[ni]);
                    mma16816(acc[mi][ni], ah[mi], bl[ni]);
                    mma16816(acc[mi][ni], al[mi], bh[ni]);
                }
        }
        __syncthreads();
        if (ch + NSTAGE < KC) load_chunk(ch + NSTAGE, (ch + NSTAGE) % NSTAGE);
        else asm volatile("cp.async.commit_group;" ::: "memory");
    }

    // epilogue: lane l of (mi,ni): rows bm+wm*32+mi*16 + l/4 (+8), cols +(l%4)*2
    const int rbase = bm + wm * 32 + (lane >> 2);
    const int cbase = bn + wn * 64 + (lane & 3) * 2;
#pragma unroll
    for (int mi = 0; mi < 2; mi++) {
#pragma unroll
        for (int ni = 0; ni < 8; ni++) {
            const int col = cbase + ni * 8;
            float b0 = 0.f, b1 = 0.f;
            if (bias) { b0 = __ldg(bias + col); b1 = __ldg(bias + col + 1); }
            float* p0 = C + (size_t)(rbase + mi * 16) * N + col;
            float* p1 = C + (size_t)(rbase + mi * 16 + 8) * N + col;
            *(float2*)p0 = make_float2(acc[mi][ni][0] + b0, acc[mi][ni][1] + b1);
            *(float2*)p1 = make_float2(acc[mi][ni][2] + b0, acc[mi][ni][3] + b1);
        }
    }
}

// ---------------------------------------------------------------------------
// Covering-window enumeration
// ---------------------------------------------------------------------------
__device__ __forceinline__ int covers(int r, int lim, int tys[2], int iis[2])
{
    const int th = (r + 1) >> 1;
    const int ih = (r + 1) & 1;
    int n = 0;
    if (th < lim) { tys[n] = th;     iis[n] = ih;     n++; }
    if (th >= 1)  { tys[n] = th - 1; iis[n] = ih + 2; n++; }
    return n;
}

// ---------------------------------------------------------------------------
// Phase 1: exp(logits) -> g_E, per-(head,pixel) sums -> g_S
// ---------------------------------------------------------------------------
__global__ __launch_bounds__(256)
void attn_phase1(const float* __restrict__ Q, const float* __restrict__ KV,
                 const float* __restrict__ rel_init,
                 const float* __restrict__ rel_bias)
{
    const int pix = blockIdx.x * 4 + (threadIdx.x >> 6);
    const int j   = threadIdx.x & 63;
    const int b   = pix >> 14;
    const int rc  = pix & (NPIX - 1);
    const int r   = rc >> 7;
    const int c   = rc & (WB - 1);
    const int h   = j >> 3;
    const int l8  = j & 7;

    const float4 q = *(const float4*)(Q + (size_t)pix * DIM + j * 4);

    int tys[2], iis[2], txs[2], jjs[2];
    const int nty = covers(r, HT, tys, iis);
    const int ntx = covers(c, WT, txs, jjs);

    float ssum = 0.f;
#pragma unroll
    for (int a = 0; a < 2; a++) {
        if (a >= nty) break;
#pragma unroll
        for (int e = 0; e < 2; e++) {
            if (e >= ntx) break;
            const int w = tys[a] * WT + txs[e];
            const int p = iis[a] * 4 + jjs[e];
            const float4 kk = *(const float4*)(KV + (size_t)(b * NWIN + w) * KVD + j * 4);
            float part = q.x * kk.x + q.y * kk.y + q.z * kk.z + q.w * kk.w;
            part += __shfl_xor_sync(0xffffffffu, part, 4);
            part += __shfl_xor_sync(0xffffffffu, part, 2);
            part += __shfl_xor_sync(0xffffffffu, part, 1);
            const float logit = part * ATT_SCALE + rel_init[p] + rel_bias[p];
            const float ex = expf(logit);
            ssum += ex;
            if (l8 == 0)
                g_E[((size_t)(b * NWIN + w) * HEADS + h) * 16 + p] = ex;
        }
    }
    if (l8 == 0)
        g_S[(size_t)(b * HEADS + h) * NPIX + rc] = ssum;
}

// ---------------------------------------------------------------------------
// Phase 2: scrambled normalization (faithful to reference reshape), V weight,
// fold; writes hi/lo bf16 split of P directly.
// ---------------------------------------------------------------------------
__global__ __launch_bounds__(256)
void attn_phase2(const float* __restrict__ KV,
                 __nv_bfloat16* __restrict__ Phi, __nv_bfloat16* __restrict__ Plo)
{
    const int pix = blockIdx.x * 4 + (threadIdx.x >> 6);
    const int j   = threadIdx.x & 63;
    const int b   = pix >> 14;
    const int rc  = pix & (NPIX - 1);
    const int r   = rc >> 7;
    const int c   = rc & (WB - 1);
    const int h   = j >> 3;

    int tys[2], iis[2], txs[2], jjs[2];
    const int nty = covers(r, HT, tys, iis);
    const int ntx = covers(c, WT, txs, jjs);

    float4 out = make_float4(0.f, 0.f, 0.f, 0.f);
#pragma unroll
    for (int a = 0; a < 2; a++) {
        if (a >= nty) break;
#pragma unroll
        for (int e = 0; e < 2; e++) {
            if (e >= ntx) break;
            const int w = tys[a] * WT + txs[e];
            const int p = iis[a] * 4 + jjs[e];

            const float ex = g_E[((size_t)(b * NWIN + w) * HEADS + h) * 16 + p];

            const int h2 = w >> 9;
            const int w2 = ((w & 511) << 3) + h;
            const int r2 = 2 * (w2 >> 6) - 1 + (p >> 2);
            const int c2 = 2 * (w2 & 63) - 1 + (p & 3);
            float denom = 1.f;
            if ((unsigned)r2 < (unsigned)HB && (unsigned)c2 < (unsigned)WB)
                denom = g_S[(size_t)(b * HEADS + h2) * NPIX + r2 * WB + c2];

            const float wgt = ex / denom;
            const float4 v = *(const float4*)(KV + (size_t)(b * NWIN + w) * KVD + DIM + j * 4);
            out.x = fmaf(wgt, v.x, out.x);
            out.y = fmaf(wgt, v.y, out.y);
            out.z = fmaf(wgt, v.z, out.z);
            out.w = fmaf(wgt, v.w, out.w);
        }
    }

    float xs[4] = {out.x, out.y, out.z, out.w};
    unsigned short hb[4], lb[4];
#pragma unroll
    for (int k = 0; k < 4; k++) {
        __nv_bfloat16 hi = __float2bfloat16(xs[k]);
        __nv_bfloat16 lo = __float2bfloat16(xs[k] - __bfloat162float(hi));
        hb[k] = __bfloat16_as_ushort(hi);
        lb[k] = __bfloat16_as_ushort(lo);
    }
    const size_t idx = ((size_t)pix * DIM + j * 4) / 4;
    ((ushort4*)Phi)[idx] = make_ushort4(hb[0], hb[1], hb[2], hb[3]);
    ((ushort4*)Plo)[idx] = make_ushort4(lb[0], lb[1], lb[2], lb[3]);
}

// ---------------------------------------------------------------------------
// Launch
// ---------------------------------------------------------------------------
extern "C" void kernel_launch(void* const* d_in, const int* in_sizes, int n_in,
                              void* d_out, int out_size)
{
    (void)in_sizes; (void)n_in; (void)out_size;
    const float* Xt       = (const float*)d_in[0];
    const float* Xb       = (const float*)d_in[1];
    const float* q_w      = (const float*)d_in[2];
    const float* kv_w     = (const float*)d_in[3];
    const float* proj_w   = (const float*)d_in[4];
    const float* proj_b   = (const float*)d_in[5];
    const float* rel_init = (const float*)d_in[6];
    const float* rel_bias = (const float*)d_in[7];
    float* out = (float*)d_out;

    float *Qb, *KVb;
    __nv_bfloat16 *Xbh, *Xbl, *Xth, *Xtl, *Ph, *Pl;
    __nv_bfloat16 *wqh, *wql, *wkh, *wkl, *wph, *wpl;
    cudaGetSymbolAddress((void**)&Qb,  g_Q);
    cudaGetSymbolAddress((void**)&KVb, g_KV);
    cudaGetSymbolAddress((void**)&Xbh, g_Xbh);
    cudaGetSymbolAddress((void**)&Xbl, g_Xbl);
    cudaGetSymbolAddress((void**)&Xth, g_Xth);
    cudaGetSymbolAddress((void**)&Xtl, g_Xtl);
    cudaGetSymbolAddress((void**)&Ph,  g_Ph);
    cudaGetSymbolAddress((void**)&Pl,  g_Pl);
    cudaGetSymbolAddress((void**)&wqh, g_wqh);
    cudaGetSymbolAddress((void**)&wql, g_wql);
    cudaGetSymbolAddress((void**)&wkh, g_wkh);
    cudaGetSymbolAddress((void**)&wkl, g_wkl);
    cudaGetSymbolAddress((void**)&wph, g_wph);
    cudaGetSymbolAddress((void**)&wpl, g_wpl);

    cudaFuncSetAttribute(gemm_split,
                         cudaFuncAttributeMaxDynamicSharedMemorySize, GEMM_SMEM);

    // splits
    {
        int n4 = (BATCH * NPIX * DIM) / 4;
        split_f32<<<(n4 + 255) / 256, 256>>>(Xb, Xbh, Xbl, n4);
    }
    {
        int n4 = (BATCH * NWIN * KVD) / 4;
        split_f32<<<(n4 + 255) / 256, 256>>>(Xt, Xth, Xtl, n4);
    }
    split_f32<<<(DIM * DIM / 4 + 255) / 256, 256>>>(q_w,    wqh, wql, DIM * DIM / 4);
    split_f32<<<(KVD * KVD / 4 + 255) / 256, 256>>>(kv_w,   wkh, wkl, KVD * KVD / 4);
    split_f32<<<(DIM * DIM / 4 + 255) / 256, 256>>>(proj_w, wph, wpl, DIM * DIM / 4);

    // 1) Q = Xb @ q_w^T   (65536 x 256 x 256)
    gemm_split<<<dim3(DIM / TBN, (BATCH * NPIX) / TBM), 256, GEMM_SMEM>>>(
        Xbh, Xbl, wqh, wql, nullptr, Qb, BATCH * NPIX, DIM, DIM);

    // 2) KV = Xt @ kv_w^T (16384 x 512 x 512)
    gemm_split<<<dim3(KVD / TBN, (BATCH * NWIN) / TBM), 256, GEMM_SMEM>>>(
        Xth, Xtl, wkh, wkl, nullptr, KVb, BATCH * NWIN, KVD, KVD);

    // 3) attention numerators + sums
    attn_phase1<<<(BATCH * NPIX) / 4, 256>>>(Qb, KVb, rel_init, rel_bias);

    // 4) normalization + V + fold (writes split P)
    attn_phase2<<<(BATCH * NPIX) / 4, 256>>>(KVb, Ph, Pl);

    // 5) Out = P @ proj_w^T + proj_b  (65536 x 256 x 256)
    gemm_split<<<dim3(DIM / TBN, (BATCH * NPIX) / TBM), 256, GEMM_SMEM>>>(
        Ph, Pl, wph, wpl, proj_b, out, BATCH * NPIX, DIM, DIM);
}

// round 7
// speedup vs baseline: 2.9930x; 1.2059x over previous
#include <cuda_runtime.h>
#include <cuda_bf16.h>
#include <cstdint>

// ---------------------------------------------------------------------------
// Problem constants
// ---------------------------------------------------------------------------
#define HEADS 8
#define DIM   256
#define KVD   512
#define HB    128
#define WB    128
#define HT    64
#define WT    64
#define NPIX  16384
#define NWIN  4096
#define BATCH 4
#define ATT_SCALE 0.17677669529663687f

// ---------------------------------------------------------------------------
// Scratch (device globals)
// ---------------------------------------------------------------------------
__device__ float g_Q [BATCH * NPIX * DIM];
__device__ float g_KV[BATCH * NWIN * KVD];
__device__ float g_E [BATCH * NWIN * HEADS * 16];
__device__ float g_S [BATCH * HEADS * NPIX];

__device__ __nv_bfloat16 g_Xbh[BATCH * NPIX * DIM];
__device__ __nv_bfloat16 g_Xbl[BATCH * NPIX * DIM];
__device__ __nv_bfloat16 g_Xth[BATCH * NWIN * KVD];
__device__ __nv_bfloat16 g_Xtl[BATCH * NWIN * KVD];
__device__ __nv_bfloat16 g_Ph [BATCH * NPIX * DIM];
__device__ __nv_bfloat16 g_Pl [BATCH * NPIX * DIM];
__device__ __nv_bfloat16 g_wqh[DIM * DIM],  g_wql[DIM * DIM];
__device__ __nv_bfloat16 g_wkh[KVD * KVD],  g_wkl[KVD * KVD];
__device__ __nv_bfloat16 g_wph[DIM * DIM],  g_wpl[DIM * DIM];

// ---------------------------------------------------------------------------
// Helpers
// ---------------------------------------------------------------------------
__device__ __forceinline__ uint32_t smem_u32(const void* p) {
    uint32_t a;
    asm("{ .reg .u64 t; cvta.to.shared.u64 t, %1; cvt.u32.u64 %0, t; }"
        : "=r"(a) : "l"(p));
    return a;
}
__device__ __forceinline__ void cpasync16(uint32_t s, const void* g) {
    asm volatile("cp.async.cg.shared.global [%0], [%1], 16;" :: "r"(s), "l"(g));
}
__device__ __forceinline__ void ldm_x4(uint32_t* r, uint32_t addr) {
    asm volatile("ldmatrix.sync.aligned.m8n8.x4.shared.b16 {%0,%1,%2,%3}, [%4];"
                 : "=r"(r[0]), "=r"(r[1]), "=r"(r[2]), "=r"(r[3]) : "r"(addr));
}
__device__ __forceinline__ void mma16816(float* c, const uint32_t* a, const uint32_t* b) {
    asm volatile("mma.sync.aligned.m16n8k16.row.col.f32.bf16.bf16.f32 "
                 "{%0,%1,%2,%3}, {%4,%5,%6,%7}, {%8,%9}, {%0,%1,%2,%3};"
                 : "+f"(c[0]), "+f"(c[1]), "+f"(c[2]), "+f"(c[3])
                 : "r"(a[0]), "r"(a[1]), "r"(a[2]), "r"(a[3]),
                   "r"(b[0]), "r"(b[1]));
}
// swizzled byte offset of (row r, 16B-chunk c) inside a [128 x 64B] tile
__device__ __forceinline__ uint32_t sw_off(int r, int c) {
    return (uint32_t)(r * 64 + ((c ^ ((r >> 1) & 3)) << 4));
}

// ---------------------------------------------------------------------------
// Split fp32 -> (hi, lo) bf16
// ---------------------------------------------------------------------------
__global__ __launch_bounds__(256)
void split_f32(const float* __restrict__ x, __nv_bfloat16* __restrict__ hi,
               __nv_bfloat16* __restrict__ lo, int n4)
{
    int i = blockIdx.x * blockDim.x + threadIdx.x;
    if (i >= n4) return;
    float4 v = ((const float4*)x)[i];
    float xs[4] = {v.x, v.y, v.z, v.w};
    unsigned short hb[4], lb[4];
#pragma unroll
    for (int k = 0; k < 4; k++) {
        __nv_bfloat16 h = __float2bfloat16(xs[k]);
        __nv_bfloat16 l = __float2bfloat16(xs[k] - __bfloat162float(h));
        hb[k] = __bfloat16_as_ushort(h);
        lb[k] = __bfloat16_as_ushort(l);
    }
    ((ushort4*)hi)[i] = make_ushort4(hb[0], hb[1], hb[2], hb[3]);
    ((ushort4*)lo)[i] = make_ushort4(lb[0], lb[1], lb[2], lb[3]);
}

// ---------------------------------------------------------------------------
// HMMA split-bf16 GEMM: C[m,n] = sum_k A[m,k]*B[n,k] (+bias[n]), fp32 out.
// 3 products per chunk: Ah*Bh + Ah*Bl + Al*Bh. Tile 128x128, BK=32, 8 warps
// (warp tile 32x64), 3-stage cp.async pipeline, ONE barrier per chunk,
// 2 CTAs/SM.
// ---------------------------------------------------------------------------
#define TBM 128
#define TBN 128
#define TBK 32
#define TILE_B   8192                 // one [128 x 64B] tile
#define STAGE_B  (4 * TILE_B)        // Ah | Al | Bh | Bl
#define NSTAGE   3
#define GEMM_SMEM (NSTAGE * STAGE_B) // 96 KB

__global__ __launch_bounds__(256, 2)
void gemm_split(const __nv_bfloat16* __restrict__ Ahi,
                const __nv_bfloat16* __restrict__ Alo,
                const __nv_bfloat16* __restrict__ Bhi,
                const __nv_bfloat16* __restrict__ Blo,
                const float* __restrict__ bias,
                float* __restrict__ C,
                int M, int N, int K)
{
    extern __shared__ char dsm[];
    const uint32_t sbase = smem_u32(dsm);

    const int tid  = threadIdx.x;
    const int wid  = tid >> 5;
    const int lane = tid & 31;
    const int wm   = wid & 3;        // 4 warps along M
    const int wn   = wid >> 2;       // 2 warps along N
    const int bm   = blockIdx.y * TBM;
    const int bn   = blockIdx.x * TBN;
    const int KC   = K / TBK;

    float acc[2][8][4];
#pragma unroll
    for (int mi = 0; mi < 2; mi++)
#pragma unroll
        for (int ni = 0; ni < 8; ni++)
#pragma unroll
            for (int q = 0; q < 4; q++) acc[mi][ni][q] = 0.f;

    auto load_chunk = [&](int ch, int stage) {
        const int k0 = ch * TBK;
        const uint32_t st = sbase + stage * STAGE_B;
#pragma unroll
        for (int t2 = 0; t2 < 2; t2++) {
            const int id = tid + t2 * 256;   // 0..511
            const int r  = id >> 2;
            const int c  = id & 3;
            const uint32_t off = sw_off(r, c);
            const size_t ga = (size_t)(bm + r) * K + k0 + c * 8;
            const size_t gb = (size_t)(bn + r) * K + k0 + c * 8;
            cpasync16(st + 0 * TILE_B + off, Ahi + ga);
            cpasync16(st + 1 * TILE_B + off, Alo + ga);
            cpasync16(st + 2 * TILE_B + off, Bhi + gb);
            cpasync16(st + 3 * TILE_B + off, Blo + gb);
        }
        asm volatile("cp.async.commit_group;" ::: "memory");
    };

    // prologue: stages 0,1 in flight
    load_chunk(0, 0);
    if (KC > 1) load_chunk(1, 1); else asm volatile("cp.async.commit_group;" ::: "memory");

    for (int ch = 0; ch < KC; ch++) {
        asm volatile("cp.async.wait_group 1;" ::: "memory");  // chunk ch resident
        __syncthreads();                                      // visible to all; all warps past ch-1
        if (ch + 2 < KC) load_chunk(ch + 2, (ch + 2) % NSTAGE);  // overwrites stage (ch-1)%3
        else asm volatile("cp.async.commit_group;" ::: "memory");

        const uint32_t st = sbase + (ch % NSTAGE) * STAGE_B;
#pragma unroll
        for (int ks = 0; ks < 2; ks++) {
            uint32_t ah[2][4], al[2][4];
#pragma unroll
            for (int mi = 0; mi < 2; mi++) {
                const int r = wm * 32 + mi * 16 + ((lane >> 3) & 1) * 8 + (lane & 7);
                const int c = ks * 2 + (lane >> 4);
                const uint32_t off = sw_off(r, c);
                ldm_x4(ah[mi], st + 0 * TILE_B + off);
                ldm_x4(al[mi], st + 1 * TILE_B + off);
            }
#pragma unroll
            for (int g = 0; g < 4; g++) {
                const int r = wn * 64 + g * 16 + ((lane >> 4) & 1) * 8 + (lane & 7);
                const int c = ks * 2 + ((lane >> 3) & 1);
                const uint32_t off = sw_off(r, c);
                uint32_t th[4], tl[4];
                ldm_x4(th, st + 2 * TILE_B + off);
                ldm_x4(tl, st + 3 * TILE_B + off);
#pragma unroll
                for (int mi = 0; mi < 2; mi++) {
                    mma16816(acc[mi][2 * g],     ah[mi], th);
                    mma16816(acc[mi][2 * g],     ah[mi], tl);
                    mma16816(acc[mi][2 * g],     al[mi], th);
                    mma16816(acc[mi][2 * g + 1], ah[mi], th + 2);
                    mma16816(acc[mi][2 * g + 1], ah[mi], tl + 2);
                    mma16816(acc[mi][2 * g + 1], al[mi], th + 2);
                }
            }
        }
    }

    // epilogue
    const int rbase = bm + wm * 32 + (lane >> 2);
    const int cbase = bn + wn * 64 + (lane & 3) * 2;
#pragma unroll
    for (int mi = 0; mi < 2; mi++) {
#pragma unroll
        for (int ni = 0; ni < 8; ni++) {
            const int col = cbase + ni * 8;
            float b0 = 0.f, b1 = 0.f;
            if (bias) { b0 = __ldg(bias + col); b1 = __ldg(bias + col + 1); }
            float* p0 = C + (size_t)(rbase + mi * 16) * N + col;
            float* p1 = C + (size_t)(rbase + mi * 16 + 8) * N + col;
            *(float2*)p0 = make_float2(acc[mi][ni][0] + b0, acc[mi][ni][1] + b1);
            *(float2*)p1 = make_float2(acc[mi][ni][2] + b0, acc[mi][ni][3] + b1);
        }
    }
}

// ---------------------------------------------------------------------------
// Covering-window enumeration
// ---------------------------------------------------------------------------
__device__ __forceinline__ int covers(int r, int lim, int tys[2], int iis[2])
{
    const int th = (r + 1) >> 1;
    const int ih = (r + 1) & 1;
    int n = 0;
    if (th < lim) { tys[n] = th;     iis[n] = ih;     n++; }
    if (th >= 1)  { tys[n] = th - 1; iis[n] = ih + 2; n++; }
    return n;
}

// ---------------------------------------------------------------------------
// Phase 1: exp(logits) -> g_E, per-(head,pixel) sums -> g_S
// ---------------------------------------------------------------------------
__global__ __launch_bounds__(256)
void attn_phase1(const float* __restrict__ Q, const float* __restrict__ KV,
                 const float* __restrict__ rel_init,
                 const float* __restrict__ rel_bias)
{
    const int pix = blockIdx.x * 4 + (threadIdx.x >> 6);
    const int j   = threadIdx.x & 63;
    const int b   = pix >> 14;
    const int rc  = pix & (NPIX - 1);
    const int r   = rc >> 7;
    const int c   = rc & (WB - 1);
    const int h   = j >> 3;
    const int l8  = j & 7;

    const float4 q = *(const float4*)(Q + (size_t)pix * DIM + j * 4);

    int tys[2], iis[2], txs[2], jjs[2];
    const int nty = covers(r, HT, tys, iis);
    const int ntx = covers(c, WT, txs, jjs);

    float ssum = 0.f;
#pragma unroll
    for (int a = 0; a < 2; a++) {
        if (a >= nty) break;
#pragma unroll
        for (int e = 0; e < 2; e++) {
            if (e >= ntx) break;
            const int w = tys[a] * WT + txs[e];
            const int p = iis[a] * 4 + jjs[e];
            const float4 kk = *(const float4*)(KV + (size_t)(b * NWIN + w) * KVD + j * 4);
            float part = q.x * kk.x + q.y * kk.y + q.z * kk.z + q.w * kk.w;
            part += __shfl_xor_sync(0xffffffffu, part, 4);
            part += __shfl_xor_sync(0xffffffffu, part, 2);
            part += __shfl_xor_sync(0xffffffffu, part, 1);
            const float logit = part * ATT_SCALE + rel_init[p] + rel_bias[p];
            const float ex = expf(logit);
            ssum += ex;
            if (l8 == 0)
                g_E[((size_t)(b * NWIN + w) * HEADS + h) * 16 + p] = ex;
        }
    }
    if (l8 == 0)
        g_S[(size_t)(b * HEADS + h) * NPIX + rc] = ssum;
}

// ---------------------------------------------------------------------------
// Phase 2: weights staged in smem (computed once per (pixel,slot,head) by 32
// threads), then pure V-FMA fold by 64 threads; writes hi/lo bf16 split of P.
// Scrambled divisor faithful to the reference reshape.
// ---------------------------------------------------------------------------
__global__ __launch_bounds__(256)
void attn_phase2(const float* __restrict__ KV,
                 __nv_bfloat16* __restrict__ Phi, __nv_bfloat16* __restrict__ Plo)
{
    __shared__ float s_wgt[4][32];   // [pixel-in-block][slot*8 + head]
    __shared__ int   s_win[4][4];    // [pixel-in-block][slot]

    const int pg  = threadIdx.x >> 6;
    const int j   = threadIdx.x & 63;
    const int pix = blockIdx.x * 4 + pg;
    const int b   = pix >> 14;
    const int rc  = pix & (NPIX - 1);
    const int r   = rc >> 7;
    const int c   = rc & (WB - 1);

    if (j < 32) {
        const int slot = j >> 3;   // a*2 + e
        const int h    = j & 7;
        int tys[2], iis[2], txs[2], jjs[2];
        const int nty = covers(r, HT, tys, iis);
        const int ntx = covers(c, WT, txs, jjs);
        const int a = slot >> 1;
        const int e = slot & 1;
        float wgt = 0.f;
        int   w   = 0;
        if (a < nty && e < ntx) {
            w = tys[a] * WT + txs[e];
            const int p = iis[a] * 4 + jjs[e];
            const float ex = g_E[((size_t)(b * NWIN + w) * HEADS + h) * 16 + p];
            const int h2 = w >> 9;
            const int w2 = ((w & 511) << 3) + h;
            const int r2 = 2 * (w2 >> 6) - 1 + (p >> 2);
            const int c2 = 2 * (w2 & 63) - 1 + (p & 3);
            float denom = 1.f;
            if ((unsigned)r2 < (unsigned)HB && (unsigned)c2 < (unsigned)WB)
                denom = g_S[(size_t)(b * HEADS + h2) * NPIX + r2 * WB + c2];
            wgt = ex / denom;
        }
        s_wgt[pg][slot * 8 + h] = wgt;
        if (h == 0) s_win[pg][slot] = w;
    }
    __syncthreads();

    const int h = j >> 3;
    float4 out = make_float4(0.f, 0.f, 0.f, 0.f);
#pragma unroll
    for (int slot = 0; slot < 4; slot++) {
        const float wgt = s_wgt[pg][slot * 8 + h];
        const int   w   = s_win[pg][slot];
        const float4 v = *(const float4*)(KV + (size_t)(b * NWIN + w) * KVD + DIM + j * 4);
        out.x = fmaf(wgt, v.x, out.x);
        out.y = fmaf(wgt, v.y, out.y);
        out.z = fmaf(wgt, v.z, out.z);
        out.w = fmaf(wgt, v.w, out.w);
    }

    float xs[4] = {out.x, out.y, out.z, out.w};
    unsigned short hb[4], lb[4];
#pragma unroll
    for (int k = 0; k < 4; k++) {
        __nv_bfloat16 hi = __float2bfloat16(xs[k]);
        __nv_bfloat16 lo = __float2bfloat16(xs[k] - __bfloat162float(hi));
        hb[k] = __bfloat16_as_ushort(hi);
        lb[k] = __bfloat16_as_ushort(lo);
    }
    const size_t idx = ((size_t)pix * DIM + j * 4) / 4;
    ((ushort4*)Phi)[idx] = make_ushort4(hb[0], hb[1], hb[2], hb[3]);
    ((ushort4*)Plo)[idx] = make_ushort4(lb[0], lb[1], lb[2], lb[3]);
}

// ---------------------------------------------------------------------------
// Launch
// ---------------------------------------------------------------------------
extern "C" void kernel_launch(void* const* d_in, const int* in_sizes, int n_in,
                              void* d_out, int out_size)
{
    (void)in_sizes; (void)n_in; (void)out_size;
    const float* Xt       = (const float*)d_in[0];
    const float* Xb       = (const float*)d_in[1];
    const float* q_w      = (const float*)d_in[2];
    const float* kv_w     = (const float*)d_in[3];
    const float* proj_w   = (const float*)d_in[4];
    const float* proj_b   = (const float*)d_in[5];
    const float* rel_init = (const float*)d_in[6];
    const float* rel_bias = (const float*)d_in[7];
    float* out = (float*)d_out;

    float *Qb, *KVb;
    __nv_bfloat16 *Xbh, *Xbl, *Xth, *Xtl, *Ph, *Pl;
    __nv_bfloat16 *wqh, *wql, *wkh, *wkl, *wph, *wpl;
    cudaGetSymbolAddress((void**)&Qb,  g_Q);
    cudaGetSymbolAddress((void**)&KVb, g_KV);
    cudaGetSymbolAddress((void**)&Xbh, g_Xbh);
    cudaGetSymbolAddress((void**)&Xbl, g_Xbl);
    cudaGetSymbolAddress((void**)&Xth, g_Xth);
    cudaGetSymbolAddress((void**)&Xtl, g_Xtl);
    cudaGetSymbolAddress((void**)&Ph,  g_Ph);
    cudaGetSymbolAddress((void**)&Pl,  g_Pl);
    cudaGetSymbolAddress((void**)&wqh, g_wqh);
    cudaGetSymbolAddress((void**)&wql, g_wql);
    cudaGetSymbolAddress((void**)&wkh, g_wkh);
    cudaGetSymbolAddress((void**)&wkl, g_wkl);
    cudaGetSymbolAddress((void**)&wph, g_wph);
    cudaGetSymbolAddress((void**)&wpl, g_wpl);

    cudaFuncSetAttribute(gemm_split,
                         cudaFuncAttributeMaxDynamicSharedMemorySize, GEMM_SMEM);

    // splits
    {
        int n4 = (BATCH * NPIX * DIM) / 4;
        split_f32<<<(n4 + 255) / 256, 256>>>(Xb, Xbh, Xbl, n4);
    }
    {
        int n4 = (BATCH * NWIN * KVD) / 4;
        split_f32<<<(n4 + 255) / 256, 256>>>(Xt, Xth, Xtl, n4);
    }
    split_f32<<<(DIM * DIM / 4 + 255) / 256, 256>>>(q_w,    wqh, wql, DIM * DIM / 4);
    split_f32<<<(KVD * KVD / 4 + 255) / 256, 256>>>(kv_w,   wkh, wkl, KVD * KVD / 4);
    split_f32<<<(DIM * DIM / 4 + 255) / 256, 256>>>(proj_w, wph, wpl, DIM * DIM / 4);

    // 1) Q = Xb @ q_w^T   (65536 x 256 x 256)
    gemm_split<<<dim3(DIM / TBN, (BATCH * NPIX) / TBM), 256, GEMM_SMEM>>>(
        Xbh, Xbl, wqh, wql, nullptr, Qb, BATCH * NPIX, DIM, DIM);

    // 2) KV = Xt @ kv_w^T (16384 x 512 x 512)
    gemm_split<<<dim3(KVD / TBN, (BATCH * NWIN) / TBM), 256, GEMM_SMEM>>>(
        Xth, Xtl, wkh, wkl, nullptr, KVb, BATCH * NWIN, KVD, KVD);

    // 3) attention numerators + sums
    attn_phase1<<<(BATCH * NPIX) / 4, 256>>>(Qb, KVb, rel_init, rel_bias);

    // 4) normalization + V + fold (writes split P)
    attn_phase2<<<(BATCH * NPIX) / 4, 256>>>(KVb, Ph, Pl);

    // 5) Out = P @ proj_w^T + proj_b  (65536 x 256 x 256)
    gemm_split<<<dim3(DIM / TBN, (BATCH * NPIX) / TBM), 256, GEMM_SMEM>>>(
        Ph, Pl, wph, wpl, proj_b, out, BATCH * NPIX, DIM, DIM);
}

// round 8
// speedup vs baseline: 3.1017x; 1.0363x over previous
#include <cuda_runtime.h>
#include <cuda_bf16.h>
#include <cstdint>

// ---------------------------------------------------------------------------
// Problem constants
// ---------------------------------------------------------------------------
#define HEADS 8
#define DIM   256
#define KVD   512
#define HB    128
#define WB    128
#define HT    64
#define WT    64
#define NPIX  16384
#define NWIN  4096
#define BATCH 4
#define ATT_SCALE 0.17677669529663687f

// ---------------------------------------------------------------------------
// Scratch (device globals)
// ---------------------------------------------------------------------------
__device__ float g_Q [BATCH * NPIX * DIM];
__device__ float g_KV[BATCH * NWIN * KVD];
__device__ float g_E [BATCH * NWIN * HEADS * 16];
__device__ float g_S [BATCH * HEADS * NPIX];

__device__ __nv_bfloat16 g_Xbh[BATCH * NPIX * DIM];
__device__ __nv_bfloat16 g_Xbl[BATCH * NPIX * DIM];
__device__ __nv_bfloat16 g_Xth[BATCH * NWIN * KVD];
__device__ __nv_bfloat16 g_Xtl[BATCH * NWIN * KVD];
__device__ __nv_bfloat16 g_Ph [BATCH * NPIX * DIM];
__device__ __nv_bfloat16 g_Pl [BATCH * NPIX * DIM];
__device__ __nv_bfloat16 g_wqh[DIM * DIM],  g_wql[DIM * DIM];
__device__ __nv_bfloat16 g_wkh[KVD * KVD],  g_wkl[KVD * KVD];
__device__ __nv_bfloat16 g_wph[DIM * DIM],  g_wpl[DIM * DIM];

// ---------------------------------------------------------------------------
// Helpers
// ---------------------------------------------------------------------------
__device__ __forceinline__ uint32_t smem_u32(const void* p) {
    uint32_t a;
    asm("{ .reg .u64 t; cvta.to.shared.u64 t, %1; cvt.u32.u64 %0, t; }"
        : "=r"(a) : "l"(p));
    return a;
}
__device__ __forceinline__ void cpasync16(uint32_t s, const void* g) {
    asm volatile("cp.async.cg.shared.global [%0], [%1], 16;" :: "r"(s), "l"(g));
}
__device__ __forceinline__ void ldm_x4(uint32_t* r, uint32_t addr) {
    asm volatile("ldmatrix.sync.aligned.m8n8.x4.shared.b16 {%0,%1,%2,%3}, [%4];"
                 : "=r"(r[0]), "=r"(r[1]), "=r"(r[2]), "=r"(r[3]) : "r"(addr));
}
__device__ __forceinline__ void mma16816(float* c, const uint32_t* a, const uint32_t* b) {
    asm volatile("mma.sync.aligned.m16n8k16.row.col.f32.bf16.bf16.f32 "
                 "{%0,%1,%2,%3}, {%4,%5,%6,%7}, {%8,%9}, {%0,%1,%2,%3};"
                 : "+f"(c[0]), "+f"(c[1]), "+f"(c[2]), "+f"(c[3])
                 : "r"(a[0]), "r"(a[1]), "r"(a[2]), "r"(a[3]),
                   "r"(b[0]), "r"(b[1]));
}
// swizzled byte offset of (row r, 16B-chunk c) inside a [128 x 64B] tile
__device__ __forceinline__ uint32_t sw_off(int r, int c) {
    return (uint32_t)(r * 64 + ((c ^ ((r >> 1) & 3)) << 4));
}

// ---------------------------------------------------------------------------
// Fused split: all five fp32 -> (hi,lo) bf16 conversions in one launch.
// Segments (in float4 units):
//   [0,S0): Xb   [S0,S1): Xt   [S1,S2): q_w   [S2,S3): kv_w   [S3,S4): proj_w
// ---------------------------------------------------------------------------
#define S0 (BATCH * NPIX * DIM / 4)
#define S1 (S0 + BATCH * NWIN * KVD / 4)
#define S2 (S1 + DIM * DIM / 4)
#define S3 (S2 + KVD * KVD / 4)
#define S4 (S3 + DIM * DIM / 4)

__global__ __launch_bounds__(256)
void split_all(const float* __restrict__ Xb, const float* __restrict__ Xt,
               const float* __restrict__ qw, const float* __restrict__ kw,
               const float* __restrict__ pw,
               __nv_bfloat16* __restrict__ Xbh, __nv_bfloat16* __restrict__ Xbl,
               __nv_bfloat16* __restrict__ Xth, __nv_bfloat16* __restrict__ Xtl,
               __nv_bfloat16* __restrict__ wqh, __nv_bfloat16* __restrict__ wql,
               __nv_bfloat16* __restrict__ wkh, __nv_bfloat16* __restrict__ wkl,
               __nv_bfloat16* __restrict__ wph, __nv_bfloat16* __restrict__ wpl)
{
    int i = blockIdx.x * blockDim.x + threadIdx.x;
    if (i >= S4) return;
    const float* src; __nv_bfloat16 *ph, *pl; int base;
    if (i < S0)      { src = Xb; ph = Xbh; pl = Xbl; base = 0;  }
    else if (i < S1) { src = Xt; ph = Xth; pl = Xtl; base = S0; }
    else if (i < S2) { src = qw; ph = wqh; pl = wql; base = S1; }
    else if (i < S3) { src = kw; ph = wkh; pl = wkl; base = S2; }
    else             { src = pw; ph = wph; pl = wpl; base = S3; }
    const int k = i - base;
    float4 v = ((const float4*)src)[k];
    float xs[4] = {v.x, v.y, v.z, v.w};
    unsigned short hb[4], lb[4];
#pragma unroll
    for (int q = 0; q < 4; q++) {
        __nv_bfloat16 h = __float2bfloat16(xs[q]);
        __nv_bfloat16 l = __float2bfloat16(xs[q] - __bfloat162float(h));
        hb[q] = __bfloat16_as_ushort(h);
        lb[q] = __bfloat16_as_ushort(l);
    }
    ((ushort4*)ph)[k] = make_ushort4(hb[0], hb[1], hb[2], hb[3]);
    ((ushort4*)pl)[k] = make_ushort4(lb[0], lb[1], lb[2], lb[3]);
}

// ---------------------------------------------------------------------------
// HMMA split-bf16 GEMM: C[m,n] = sum_k A[m,k]*B[n,k] (+bias[n]), fp32 out.
// 3 products: Ah*Bh + Ah*Bl + Al*Bh. Tile 128x128, BK=32, 4 warps
// (warp tile 64x64 -> 33% less LDSM traffic), 3-stage cp.async pipeline,
// one barrier per chunk, 2 CTAs/SM.
// ---------------------------------------------------------------------------
#define TBM 128
#define TBN 128
#define TBK 32
#define TILE_B   8192                 // one [128 x 64B] tile
#define STAGE_B  (4 * TILE_B)        // Ah | Al | Bh | Bl
#define NSTAGE   3
#define GEMM_SMEM (NSTAGE * STAGE_B) // 96 KB

__global__ __launch_bounds__(128, 2)
void gemm_split(const __nv_bfloat16* __restrict__ Ahi,
                const __nv_bfloat16* __restrict__ Alo,
                const __nv_bfloat16* __restrict__ Bhi,
                const __nv_bfloat16* __restrict__ Blo,
                const float* __restrict__ bias,
                float* __restrict__ C,
                int M, int N, int K)
{
    extern __shared__ char dsm[];
    const uint32_t sbase = smem_u32(dsm);

    const int tid  = threadIdx.x;
    const int wid  = tid >> 5;
    const int lane = tid & 31;
    const int wm   = wid & 1;        // 2 warps along M (64 rows each)
    const int wn   = wid >> 1;       // 2 warps along N (64 cols each)
    const int bm   = blockIdx.y * TBM;
    const int bn   = blockIdx.x * TBN;
    const int KC   = K / TBK;

    float acc[4][8][4];
#pragma unroll
    for (int mi = 0; mi < 4; mi++)
#pragma unroll
        for (int ni = 0; ni < 8; ni++)
#pragma unroll
            for (int q = 0; q < 4; q++) acc[mi][ni][q] = 0.f;

    auto load_chunk = [&](int ch, int stage) {
        const int k0 = ch * TBK;
        const uint32_t st = sbase + stage * STAGE_B;
#pragma unroll
        for (int t2 = 0; t2 < 4; t2++) {
            const int id = tid + t2 * 128;   // 0..511
            const int r  = id >> 2;
            const int c  = id & 3;
            const uint32_t off = sw_off(r, c);
            const size_t ga = (size_t)(bm + r) * K + k0 + c * 8;
            const size_t gb = (size_t)(bn + r) * K + k0 + c * 8;
            cpasync16(st + 0 * TILE_B + off, Ahi + ga);
            cpasync16(st + 1 * TILE_B + off, Alo + ga);
            cpasync16(st + 2 * TILE_B + off, Bhi + gb);
            cpasync16(st + 3 * TILE_B + off, Blo + gb);
        }
        asm volatile("cp.async.commit_group;" ::: "memory");
    };

    // prologue: stages 0,1 in flight
    load_chunk(0, 0);
    if (KC > 1) load_chunk(1, 1); else asm volatile("cp.async.commit_group;" ::: "memory");

    for (int ch = 0; ch < KC; ch++) {
        asm volatile("cp.async.wait_group 1;" ::: "memory");  // chunk ch resident
        __syncthreads();                                      // all warps done with ch-1
        if (ch + 2 < KC) load_chunk(ch + 2, (ch + 2) % NSTAGE);  // overwrites stage (ch-1)%3
        else asm volatile("cp.async.commit_group;" ::: "memory");

        const uint32_t st = sbase + (ch % NSTAGE) * STAGE_B;
#pragma unroll
        for (int ks = 0; ks < 2; ks++) {
            uint32_t ah[4][4], al[4][4];
#pragma unroll
            for (int mi = 0; mi < 4; mi++) {
                const int r = wm * 64 + mi * 16 + ((lane >> 3) & 1) * 8 + (lane & 7);
                const int c = ks * 2 + (lane >> 4);
                const uint32_t off = sw_off(r, c);
                ldm_x4(ah[mi], st + 0 * TILE_B + off);
                ldm_x4(al[mi], st + 1 * TILE_B + off);
            }
#pragma unroll
            for (int g = 0; g < 4; g++) {
                const int r = wn * 64 + g * 16 + ((lane >> 4) & 1) * 8 + (lane & 7);
                const int c = ks * 2 + ((lane >> 3) & 1);
                const uint32_t off = sw_off(r, c);
                uint32_t th[4], tl[4];
                ldm_x4(th, st + 2 * TILE_B + off);
                ldm_x4(tl, st + 3 * TILE_B + off);
#pragma unroll
                for (int mi = 0; mi < 4; mi++) {
                    mma16816(acc[mi][2 * g],     ah[mi], th);
                    mma16816(acc[mi][2 * g],     ah[mi], tl);
                    mma16816(acc[mi][2 * g],     al[mi], th);
                    mma16816(acc[mi][2 * g + 1], ah[mi], th + 2);
                    mma16816(acc[mi][2 * g + 1], ah[mi], tl + 2);
                    mma16816(acc[mi][2 * g + 1], al[mi], th + 2);
                }
            }
        }
    }

    // epilogue
    const int rbase = bm + wm * 64 + (lane >> 2);
    const int cbase = bn + wn * 64 + (lane & 3) * 2;
#pragma unroll
    for (int mi = 0; mi < 4; mi++) {
#pragma unroll
        for (int ni = 0; ni < 8; ni++) {
            const int col = cbase + ni * 8;
            float b0 = 0.f, b1 = 0.f;
            if (bias) { b0 = __ldg(bias + col); b1 = __ldg(bias + col + 1); }
            float* p0 = C + (size_t)(rbase + mi * 16) * N + col;
            float* p1 = C + (size_t)(rbase + mi * 16 + 8) * N + col;
            *(float2*)p0 = make_float2(acc[mi][ni][0] + b0, acc[mi][ni][1] + b1);
            *(float2*)p1 = make_float2(acc[mi][ni][2] + b0, acc[mi][ni][3] + b1);
        }
    }
}

// ---------------------------------------------------------------------------
// Covering-window enumeration
// ---------------------------------------------------------------------------
__device__ __forceinline__ int covers(int r, int lim, int tys[2], int iis[2])
{
    const int th = (r + 1) >> 1;
    const int ih = (r + 1) & 1;
    int n = 0;
    if (th < lim) { tys[n] = th;     iis[n] = ih;     n++; }
    if (th >= 1)  { tys[n] = th - 1; iis[n] = ih + 2; n++; }
    return n;
}

// ---------------------------------------------------------------------------
// Phase 1: exp(logits) -> g_E, per-(head,pixel) sums -> g_S
// ---------------------------------------------------------------------------
__global__ __launch_bounds__(256)
void attn_phase1(const float* __restrict__ Q, const float* __restrict__ KV,
                 const float* __restrict__ rel_init,
                 const float* __restrict__ rel_bias)
{
    const int pix = blockIdx.x * 4 + (threadIdx.x >> 6);
    const int j   = threadIdx.x & 63;
    const int b   = pix >> 14;
    const int rc  = pix & (NPIX - 1);
    const int r   = rc >> 7;
    const int c   = rc & (WB - 1);
    const int h   = j >> 3;
    const int l8  = j & 7;

    const float4 q = *(const float4*)(Q + (size_t)pix * DIM + j * 4);

    int tys[2], iis[2], txs[2], jjs[2];
    const int nty = covers(r, HT, tys, iis);
    const int ntx = covers(c, WT, txs, jjs);

    float ssum = 0.f;
#pragma unroll
    for (int a = 0; a < 2; a++) {
        if (a >= nty) break;
#pragma unroll
        for (int e = 0; e < 2; e++) {
            if (e >= ntx) break;
            const int w = tys[a] * WT + txs[e];
            const int p = iis[a] * 4 + jjs[e];
            const float4 kk = *(const float4*)(KV + (size_t)(b * NWIN + w) * KVD + j * 4);
            float part = q.x * kk.x + q.y * kk.y + q.z * kk.z + q.w * kk.w;
            part += __shfl_xor_sync(0xffffffffu, part, 4);
            part += __shfl_xor_sync(0xffffffffu, part, 2);
            part += __shfl_xor_sync(0xffffffffu, part, 1);
            const float logit = part * ATT_SCALE + rel_init[p] + rel_bias[p];
            const float ex = expf(logit);
            ssum += ex;
            if (l8 == 0)
                g_E[((size_t)(b * NWIN + w) * HEADS + h) * 16 + p] = ex;
        }
    }
    if (l8 == 0)
        g_S[(size_t)(b * HEADS + h) * NPIX + rc] = ssum;
}

// ---------------------------------------------------------------------------
// Phase 2: weights staged in smem, pure V-FMA fold by 64 threads/pixel;
// writes hi/lo bf16 split of P. Scrambled divisor faithful to the reference.
// ---------------------------------------------------------------------------
__global__ __launch_bounds__(256)
void attn_phase2(const float* __restrict__ KV,
                 __nv_bfloat16* __restrict__ Phi, __nv_bfloat16* __restrict__ Plo)
{
    __shared__ float s_wgt[4][32];   // [pixel-in-block][slot*8 + head]
    __shared__ int   s_win[4][4];    // [pixel-in-block][slot]

    const int pg  = threadIdx.x >> 6;
    const int j   = threadIdx.x & 63;
    const int pix = blockIdx.x * 4 + pg;
    const int b   = pix >> 14;
    const int rc  = pix & (NPIX - 1);
    const int r   = rc >> 7;
    const int c   = rc & (WB - 1);

    if (j < 32) {
        const int slot = j >> 3;   // a*2 + e
        const int h    = j & 7;
        int tys[2], iis[2], txs[2], jjs[2];
        const int nty = covers(r, HT, tys, iis);
        const int ntx = covers(c, WT, txs, jjs);
        const int a = slot >> 1;
        const int e = slot & 1;
        float wgt = 0.f;
        int   w   = 0;
        if (a < nty && e < ntx) {
            w = tys[a] * WT + txs[e];
            const int p = iis[a] * 4 + jjs[e];
            const float ex = g_E[((size_t)(b * NWIN + w) * HEADS + h) * 16 + p];
            const int h2 = w >> 9;
            const int w2 = ((w & 511) << 3) + h;
            const int r2 = 2 * (w2 >> 6) - 1 + (p >> 2);
            const int c2 = 2 * (w2 & 63) - 1 + (p & 3);
            float denom = 1.f;
            if ((unsigned)r2 < (unsigned)HB && (unsigned)c2 < (unsigned)WB)
                denom = g_S[(size_t)(b * HEADS + h2) * NPIX + r2 * WB + c2];
            wgt = ex / denom;
        }
        s_wgt[pg][slot * 8 + h] = wgt;
        if (h == 0) s_win[pg][slot] = w;
    }
    __syncthreads();

    const int h = j >> 3;
    float4 out = make_float4(0.f, 0.f, 0.f, 0.f);
#pragma unroll
    for (int slot = 0; slot < 4; slot++) {
        const float wgt = s_wgt[pg][slot * 8 + h];
        const int   w   = s_win[pg][slot];
        const float4 v = *(const float4*)(KV + (size_t)(b * NWIN + w) * KVD + DIM + j * 4);
        out.x = fmaf(wgt, v.x, out.x);
        out.y = fmaf(wgt, v.y, out.y);
        out.z = fmaf(wgt, v.z, out.z);
        out.w = fmaf(wgt, v.w, out.w);
    }

    float xs[4] = {out.x, out.y, out.z, out.w};
    unsigned short hb[4], lb[4];
#pragma unroll
    for (int k = 0; k < 4; k++) {
        __nv_bfloat16 hi = __float2bfloat16(xs[k]);
        __nv_bfloat16 lo = __float2bfloat16(xs[k] - __bfloat162float(hi));
        hb[k] = __bfloat16_as_ushort(hi);
        lb[k] = __bfloat16_as_ushort(lo);
    }
    const size_t idx = ((size_t)pix * DIM + j * 4) / 4;
    ((ushort4*)Phi)[idx] = make_ushort4(hb[0], hb[1], hb[2], hb[3]);
    ((ushort4*)Plo)[idx] = make_ushort4(lb[0], lb[1], lb[2], lb[3]);
}

// ---------------------------------------------------------------------------
// Launch
// ---------------------------------------------------------------------------
extern "C" void kernel_launch(void* const* d_in, const int* in_sizes, int n_in,
                              void* d_out, int out_size)
{
    (void)in_sizes; (void)n_in; (void)out_size;
    const float* Xt       = (const float*)d_in[0];
    const float* Xb       = (const float*)d_in[1];
    const float* q_w      = (const float*)d_in[2];
    const float* kv_w     = (const float*)d_in[3];
    const float* proj_w   = (const float*)d_in[4];
    const float* proj_b   = (const float*)d_in[5];
    const float* rel_init = (const float*)d_in[6];
    const float* rel_bias = (const float*)d_in[7];
    float* out = (float*)d_out;

    float *Qb, *KVb;
    __nv_bfloat16 *Xbh, *Xbl, *Xth, *Xtl, *Ph, *Pl;
    __nv_bfloat16 *wqh, *wql, *wkh, *wkl, *wph, *wpl;
    cudaGetSymbolAddress((void**)&Qb,  g_Q);
    cudaGetSymbolAddress((void**)&KVb, g_KV);
    cudaGetSymbolAddress((void**)&Xbh, g_Xbh);
    cudaGetSymbolAddress((void**)&Xbl, g_Xbl);
    cudaGetSymbolAddress((void**)&Xth, g_Xth);
    cudaGetSymbolAddress((void**)&Xtl, g_Xtl);
    cudaGetSymbolAddress((void**)&Ph,  g_Ph);
    cudaGetSymbolAddress((void**)&Pl,  g_Pl);
    cudaGetSymbolAddress((void**)&wqh, g_wqh);
    cudaGetSymbolAddress((void**)&wql, g_wql);
    cudaGetSymbolAddress((void**)&wkh, g_wkh);
    cudaGetSymbolAddress((void**)&wkl, g_wkl);
    cudaGetSymbolAddress((void**)&wph, g_wph);
    cudaGetSymbolAddress((void**)&wpl, g_wpl);

    cudaFuncSetAttribute(gemm_split,
                         cudaFuncAttributeMaxDynamicSharedMemorySize, GEMM_SMEM);

    // fused splits (one launch)
    split_all<<<(S4 + 255) / 256, 256>>>(Xb, Xt, q_w, kv_w, proj_w,
                                         Xbh, Xbl, Xth, Xtl,
                                         wqh, wql, wkh, wkl, wph, wpl);

    // 1) Q = Xb @ q_w^T   (65536 x 256 x 256)
    gemm_split<<<dim3(DIM / TBN, (BATCH * NPIX) / TBM), 128, GEMM_SMEM>>>(
        Xbh, Xbl, wqh, wql, nullptr, Qb, BATCH * NPIX, DIM, DIM);

    // 2) KV = Xt @ kv_w^T (16384 x 512 x 512)
    gemm_split<<<dim3(KVD / TBN, (BATCH * NWIN) / TBM), 128, GEMM_SMEM>>>(
        Xth, Xtl, wkh, wkl, nullptr, KVb, BATCH * NWIN, KVD, KVD);

    // 3) attention numerators + sums
    attn_phase1<<<(BATCH * NPIX) / 4, 256>>>(Qb, KVb, rel_init, rel_bias);

    // 4) normalization + V + fold (writes split P)
    attn_phase2<<<(BATCH * NPIX) / 4, 256>>>(KVb, Ph, Pl);

    // 5) Out = P @ proj_w^T + proj_b  (65536 x 256 x 256)
    gemm_split<<<dim3(DIM / TBN, (BATCH * NPIX) / TBM), 128, GEMM_SMEM>>>(
        Ph, Pl, wph, wpl, proj_b, out, BATCH * NPIX, DIM, DIM);
}

// round 9
// speedup vs baseline: 3.2809x; 1.0578x over previous
#include <cuda_runtime.h>
#include <cuda_bf16.h>
#include <cstdint>

// ---------------------------------------------------------------------------
// Problem constants
// ---------------------------------------------------------------------------
#define HEADS 8
#define DIM   256
#define KVD   512
#define HB    128
#define WB    128
#define HT    64
#define WT    64
#define NPIX  16384
#define NWIN  4096
#define BATCH 4
#define ATT_SCALE 0.17677669529663687f

// ---------------------------------------------------------------------------
// Scratch (device globals)
// ---------------------------------------------------------------------------
__device__ float g_Q [BATCH * NPIX * DIM];
__device__ float g_KV[BATCH * NWIN * KVD];
__device__ float g_E [BATCH * NWIN * HEADS * 16];
__device__ float g_S [BATCH * HEADS * NPIX];

__device__ __nv_bfloat16 g_Xbh[BATCH * NPIX * DIM];
__device__ __nv_bfloat16 g_Xbl[BATCH * NPIX * DIM];
__device__ __nv_bfloat16 g_Xth[BATCH * NWIN * KVD];
__device__ __nv_bfloat16 g_Xtl[BATCH * NWIN * KVD];
__device__ __nv_bfloat16 g_Ph [BATCH * NPIX * DIM];
__device__ __nv_bfloat16 g_Pl [BATCH * NPIX * DIM];
__device__ __nv_bfloat16 g_wqh[DIM * DIM],  g_wql[DIM * DIM];
__device__ __nv_bfloat16 g_wkh[KVD * KVD],  g_wkl[KVD * KVD];
__device__ __nv_bfloat16 g_wph[DIM * DIM],  g_wpl[DIM * DIM];

// ---------------------------------------------------------------------------
// Helpers
// ---------------------------------------------------------------------------
__device__ __forceinline__ uint32_t smem_u32(const void* p) {
    uint32_t a;
    asm("{ .reg .u64 t; cvta.to.shared.u64 t, %1; cvt.u32.u64 %0, t; }"
        : "=r"(a) : "l"(p));
    return a;
}
__device__ __forceinline__ void cpasync16(uint32_t s, const void* g) {
    asm volatile("cp.async.cg.shared.global [%0], [%1], 16;" :: "r"(s), "l"(g));
}
__device__ __forceinline__ void ldm_x4(uint32_t* r, uint32_t addr) {
    asm volatile("ldmatrix.sync.aligned.m8n8.x4.shared.b16 {%0,%1,%2,%3}, [%4];"
                 : "=r"(r[0]), "=r"(r[1]), "=r"(r[2]), "=r"(r[3]) : "r"(addr));
}
__device__ __forceinline__ void mma16816(float* c, const uint32_t* a, const uint32_t* b) {
    asm volatile("mma.sync.aligned.m16n8k16.row.col.f32.bf16.bf16.f32 "
                 "{%0,%1,%2,%3}, {%4,%5,%6,%7}, {%8,%9}, {%0,%1,%2,%3};"
                 : "+f"(c[0]), "+f"(c[1]), "+f"(c[2]), "+f"(c[3])
                 : "r"(a[0]), "r"(a[1]), "r"(a[2]), "r"(a[3]),
                   "r"(b[0]), "r"(b[1]));
}
// swizzled byte offset of (row r, 16B-chunk c) inside a [128 x 64B] tile
__device__ __forceinline__ uint32_t sw_off(int r, int c) {
    return (uint32_t)(r * 64 + ((c ^ ((r >> 1) & 3)) << 4));
}

// ---------------------------------------------------------------------------
// Fused split: all five fp32 -> (hi,lo) bf16 conversions, 2 float4/thread.
// ---------------------------------------------------------------------------
#define S0 (BATCH * NPIX * DIM / 4)
#define S1 (S0 + BATCH * NWIN * KVD / 4)
#define S2 (S1 + DIM * DIM / 4)
#define S3 (S2 + KVD * KVD / 4)
#define S4 (S3 + DIM * DIM / 4)

__device__ __forceinline__ void split_one(int i,
    const float* Xb, const float* Xt, const float* qw, const float* kw,
    const float* pw,
    __nv_bfloat16* Xbh, __nv_bfloat16* Xbl, __nv_bfloat16* Xth, __nv_bfloat16* Xtl,
    __nv_bfloat16* wqh, __nv_bfloat16* wql, __nv_bfloat16* wkh, __nv_bfloat16* wkl,
    __nv_bfloat16* wph, __nv_bfloat16* wpl)
{
    const float* src; __nv_bfloat16 *ph, *pl; int base;
    if (i < S0)      { src = Xb; ph = Xbh; pl = Xbl; base = 0;  }
    else if (i < S1) { src = Xt; ph = Xth; pl = Xtl; base = S0; }
    else if (i < S2) { src = qw; ph = wqh; pl = wql; base = S1; }
    else if (i < S3) { src = kw; ph = wkh; pl = wkl; base = S2; }
    else             { src = pw; ph = wph; pl = wpl; base = S3; }
    const int k = i - base;
    float4 v = ((const float4*)src)[k];
    float xs[4] = {v.x, v.y, v.z, v.w};
    unsigned short hb[4], lb[4];
#pragma unroll
    for (int q = 0; q < 4; q++) {
        __nv_bfloat16 h = __float2bfloat16(xs[q]);
        __nv_bfloat16 l = __float2bfloat16(xs[q] - __bfloat162float(h));
        hb[q] = __bfloat16_as_ushort(h);
        lb[q] = __bfloat16_as_ushort(l);
    }
    ((ushort4*)ph)[k] = make_ushort4(hb[0], hb[1], hb[2], hb[3]);
    ((ushort4*)pl)[k] = make_ushort4(lb[0], lb[1], lb[2], lb[3]);
}

__global__ __launch_bounds__(256)
void split_all(const float* __restrict__ Xb, const float* __restrict__ Xt,
               const float* __restrict__ qw, const float* __restrict__ kw,
               const float* __restrict__ pw,
               __nv_bfloat16* __restrict__ Xbh, __nv_bfloat16* __restrict__ Xbl,
               __nv_bfloat16* __restrict__ Xth, __nv_bfloat16* __restrict__ Xtl,
               __nv_bfloat16* __restrict__ wqh, __nv_bfloat16* __restrict__ wql,
               __nv_bfloat16* __restrict__ wkh, __nv_bfloat16* __restrict__ wkl,
               __nv_bfloat16* __restrict__ wph, __nv_bfloat16* __restrict__ wpl)
{
    int i0 = (blockIdx.x * blockDim.x + threadIdx.x) * 2;
    if (i0 < S4)
        split_one(i0, Xb, Xt, qw, kw, pw, Xbh, Xbl, Xth, Xtl,
                  wqh, wql, wkh, wkl, wph, wpl);
    if (i0 + 1 < S4)
        split_one(i0 + 1, Xb, Xt, qw, kw, pw, Xbh, Xbl, Xth, Xtl,
                  wqh, wql, wkh, wkl, wph, wpl);
}

// ---------------------------------------------------------------------------
// HMMA split-bf16 GEMM body: C[m,n] = sum_k A[m,k]*B[n,k] (+bias[n]).
// 3 products: Ah*Bh + Ah*Bl + Al*Bh. Tile 128x128, BK=32, 4 warps (64x64
// warp tile), 3-stage cp.async pipeline, one barrier per chunk, 2 CTAs/SM.
// ---------------------------------------------------------------------------
#define TBM 128
#define TBN 128
#define TBK 32
#define TILE_B   8192                 // one [128 x 64B] tile
#define STAGE_B  (4 * TILE_B)        // Ah | Al | Bh | Bl
#define NSTAGE   3
#define GEMM_SMEM (NSTAGE * STAGE_B) // 96 KB

__device__ __forceinline__ void gemm_body(
    const __nv_bfloat16* __restrict__ Ahi, const __nv_bfloat16* __restrict__ Alo,
    const __nv_bfloat16* __restrict__ Bhi, const __nv_bfloat16* __restrict__ Blo,
    const float* __restrict__ bias, float* __restrict__ C,
    int N, int K, int bm, int bn, char* dsm)
{
    const uint32_t sbase = smem_u32(dsm);
    const int tid  = threadIdx.x;
    const int wid  = tid >> 5;
    const int lane = tid & 31;
    const int wm   = wid & 1;        // 2 warps along M (64 rows each)
    const int wn   = wid >> 1;       // 2 warps along N (64 cols each)
    const int KC   = K / TBK;

    float acc[4][8][4];
#pragma unroll
    for (int mi = 0; mi < 4; mi++)
#pragma unroll
        for (int ni = 0; ni < 8; ni++)
#pragma unroll
            for (int q = 0; q < 4; q++) acc[mi][ni][q] = 0.f;

    auto load_chunk = [&](int ch, int stage) {
        const int k0 = ch * TBK;
        const uint32_t st = sbase + stage * STAGE_B;
#pragma unroll
        for (int t2 = 0; t2 < 4; t2++) {
            const int id = tid + t2 * 128;   // 0..511
            const int r  = id >> 2;
            const int c  = id & 3;
            const uint32_t off = sw_off(r, c);
            const size_t ga = (size_t)(bm + r) * K + k0 + c * 8;
            const size_t gb = (size_t)(bn + r) * K + k0 + c * 8;
            cpasync16(st + 0 * TILE_B + off, Ahi + ga);
            cpasync16(st + 1 * TILE_B + off, Alo + ga);
            cpasync16(st + 2 * TILE_B + off, Bhi + gb);
            cpasync16(st + 3 * TILE_B + off, Blo + gb);
        }
        asm volatile("cp.async.commit_group;" ::: "memory");
    };

    load_chunk(0, 0);
    load_chunk(1, 1);

    for (int ch = 0; ch < KC; ch++) {
        asm volatile("cp.async.wait_group 1;" ::: "memory");  // chunk ch resident
        __syncthreads();                                      // all warps done with ch-1
        if (ch + 2 < KC) load_chunk(ch + 2, (ch + 2) % NSTAGE);
        else asm volatile("cp.async.commit_group;" ::: "memory");

        const uint32_t st = sbase + (ch % NSTAGE) * STAGE_B;
#pragma unroll
        for (int ks = 0; ks < 2; ks++) {
            uint32_t ah[4][4], al[4][4];
#pragma unroll
            for (int mi = 0; mi < 4; mi++) {
                const int r = wm * 64 + mi * 16 + ((lane >> 3) & 1) * 8 + (lane & 7);
                const int c = ks * 2 + (lane >> 4);
                const uint32_t off = sw_off(r, c);
                ldm_x4(ah[mi], st + 0 * TILE_B + off);
                ldm_x4(al[mi], st + 1 * TILE_B + off);
            }
#pragma unroll
            for (int g = 0; g < 4; g++) {
                const int r = wn * 64 + g * 16 + ((lane >> 4) & 1) * 8 + (lane & 7);
                const int c = ks * 2 + ((lane >> 3) & 1);
                const uint32_t off = sw_off(r, c);
                uint32_t th[4], tl[4];
                ldm_x4(th, st + 2 * TILE_B + off);
                ldm_x4(tl, st + 3 * TILE_B + off);
#pragma unroll
                for (int mi = 0; mi < 4; mi++) {
                    mma16816(acc[mi][2 * g],     ah[mi], th);
                    mma16816(acc[mi][2 * g],     ah[mi], tl);
                    mma16816(acc[mi][2 * g],     al[mi], th);
                    mma16816(acc[mi][2 * g + 1], ah[mi], th + 2);
                    mma16816(acc[mi][2 * g + 1], ah[mi], tl + 2);
                    mma16816(acc[mi][2 * g + 1], al[mi], th + 2);
                }
            }
        }
    }

    const int rbase = bm + wm * 64 + (lane >> 2);
    const int cbase = bn + wn * 64 + (lane & 3) * 2;
#pragma unroll
    for (int mi = 0; mi < 4; mi++) {
#pragma unroll
        for (int ni = 0; ni < 8; ni++) {
            const int col = cbase + ni * 8;
            float b0 = 0.f, b1 = 0.f;
            if (bias) { b0 = __ldg(bias + col); b1 = __ldg(bias + col + 1); }
            float* p0 = C + (size_t)(rbase + mi * 16) * N + col;
            float* p1 = C + (size_t)(rbase + mi * 16 + 8) * N + col;
            *(float2*)p0 = make_float2(acc[mi][ni][0] + b0, acc[mi][ni][1] + b1);
            *(float2*)p1 = make_float2(acc[mi][ni][2] + b0, acc[mi][ni][3] + b1);
        }
    }
}

// Fused Q-GEMM (blocks 0..1023) + KV-GEMM (blocks 1024..1535): one tail.
#define QBLKS  ((BATCH * NPIX / TBM) * (DIM / TBN))   // 512*2 = 1024
#define KVBLKS ((BATCH * NWIN / TBM) * (KVD / TBN))   // 128*4 = 512

__global__ __launch_bounds__(128, 2)
void gemm_qkv(const __nv_bfloat16* __restrict__ Xbh, const __nv_bfloat16* __restrict__ Xbl,
              const __nv_bfloat16* __restrict__ wqh, const __nv_bfloat16* __restrict__ wql,
              const __nv_bfloat16* __restrict__ Xth, const __nv_bfloat16* __restrict__ Xtl,
              const __nv_bfloat16* __restrict__ wkh, const __nv_bfloat16* __restrict__ wkl,
              float* __restrict__ Q, float* __restrict__ KV)
{
    extern __shared__ char dsm[];
    const int bid = blockIdx.x;
    if (bid < QBLKS) {
        gemm_body(Xbh, Xbl, wqh, wql, nullptr, Q,
                  DIM, DIM, (bid >> 1) * TBM, (bid & 1) * TBN, dsm);
    } else {
        const int t = bid - QBLKS;
        gemm_body(Xth, Xtl, wkh, wkl, nullptr, KV,
                  KVD, KVD, (t >> 2) * TBM, (t & 3) * TBN, dsm);
    }
}

__global__ __launch_bounds__(128, 2)
void gemm_proj(const __nv_bfloat16* __restrict__ Ph, const __nv_bfloat16* __restrict__ Pl,
               const __nv_bfloat16* __restrict__ wph, const __nv_bfloat16* __restrict__ wpl,
               const float* __restrict__ bias, float* __restrict__ C)
{
    extern __shared__ char dsm[];
    gemm_body(Ph, Pl, wph, wpl, bias, C,
              DIM, DIM, (int)blockIdx.y * TBM, (int)blockIdx.x * TBN, dsm);
}

// ---------------------------------------------------------------------------
// Covering-window enumeration
// ---------------------------------------------------------------------------
__device__ __forceinline__ int covers(int r, int lim, int tys[2], int iis[2])
{
    const int th = (r + 1) >> 1;
    const int ih = (r + 1) & 1;
    int n = 0;
    if (th < lim) { tys[n] = th;     iis[n] = ih;     n++; }
    if (th >= 1)  { tys[n] = th - 1; iis[n] = ih + 2; n++; }
    return n;
}

// ---------------------------------------------------------------------------
// Phase 1 (warp per pixel): exp(logits) -> g_E, per-(head,pixel) sums -> g_S.
// Lane: head = lane>>2, 4 lanes per head, 8 channels per lane (2x float4).
// ---------------------------------------------------------------------------
__global__ __launch_bounds__(256)
void attn_phase1(const float* __restrict__ Q, const float* __restrict__ KV,
                 const float* __restrict__ rel_init,
                 const float* __restrict__ rel_bias)
{
    __shared__ float s_rel[16];
    if (threadIdx.x < 16)
        s_rel[threadIdx.x] = rel_init[threadIdx.x] + rel_bias[threadIdx.x];
    __syncthreads();

    const int wrp  = threadIdx.x >> 5;
    const int lane = threadIdx.x & 31;
    const int pix  = blockIdx.x * 8 + wrp;
    const int b    = pix >> 14;
    const int rc   = pix & (NPIX - 1);
    const int r    = rc >> 7;
    const int c    = rc & (WB - 1);
    const int h    = lane >> 2;
    const int l4   = lane & 3;
    const int ch   = h * 32 + l4 * 8;

    const float4 q0 = *(const float4*)(Q + (size_t)pix * DIM + ch);
    const float4 q1 = *(const float4*)(Q + (size_t)pix * DIM + ch + 4);

    int tys[2], iis[2], txs[2], jjs[2];
    const int nty = covers(r, HT, tys, iis);
    const int ntx = covers(c, WT, txs, jjs);

    float ssum = 0.f;
#pragma unroll
    for (int a = 0; a < 2; a++) {
        if (a >= nty) break;
#pragma unroll
        for (int e = 0; e < 2; e++) {
            if (e >= ntx) break;
            const int w = tys[a] * WT + txs[e];
            const int p = iis[a] * 4 + jjs[e];
            const float* kp = KV + (size_t)(b * NWIN + w) * KVD + ch;
            const float4 k0 = *(const float4*)kp;
            const float4 k1 = *(const float4*)(kp + 4);
            float part = q0.x * k0.x + q0.y * k0.y + q0.z * k0.z + q0.w * k0.w
                       + q1.x * k1.x + q1.y * k1.y + q1.z * k1.z + q1.w * k1.w;
            part += __shfl_xor_sync(0xffffffffu, part, 2);
            part += __shfl_xor_sync(0xffffffffu, part, 1);
            const float ex = expf(part * ATT_SCALE + s_rel[p]);
            ssum += ex;
            if (l4 == 0)
                g_E[((size_t)(b * NWIN + w) * HEADS + h) * 16 + p] = ex;
        }
    }
    if (l4 == 0)
        g_S[(size_t)(b * HEADS + h) * NPIX + rc] = ssum;
}

// ---------------------------------------------------------------------------
// Phase 2: weights staged in smem, pure V-FMA fold by 64 threads/pixel;
// writes hi/lo bf16 split of P. Scrambled divisor faithful to the reference.
// ---------------------------------------------------------------------------
__global__ __launch_bounds__(256)
void attn_phase2(const float* __restrict__ KV,
                 __nv_bfloat16* __restrict__ Phi, __nv_bfloat16* __restrict__ Plo)
{
    __shared__ float s_wgt[4][32];   // [pixel-in-block][slot*8 + head]
    __shared__ int   s_win[4][4];    // [pixel-in-block][slot]

    const int pg  = threadIdx.x >> 6;
    const int j   = threadIdx.x & 63;
    const int pix = blockIdx.x * 4 + pg;
    const int b   = pix >> 14;
    const int rc  = pix & (NPIX - 1);
    const int r   = rc >> 7;
    const int c   = rc & (WB - 1);

    if (j < 32) {
        const int slot = j >> 3;   // a*2 + e
        const int h    = j & 7;
        int tys[2], iis[2], txs[2], jjs[2];
        const int nty = covers(r, HT, tys, iis);
        const int ntx = covers(c, WT, txs, jjs);
        const int a = slot >> 1;
        const int e = slot & 1;
        float wgt = 0.f;
        int   w   = 0;
        if (a < nty && e < ntx) {
            w = tys[a] * WT + txs[e];
            const int p = iis[a] * 4 + jjs[e];
            const float ex = g_E[((size_t)(b * NWIN + w) * HEADS + h) * 16 + p];
            const int h2 = w >> 9;
            const int w2 = ((w & 511) << 3) + h;
            const int r2 = 2 * (w2 >> 6) - 1 + (p >> 2);
            const int c2 = 2 * (w2 & 63) - 1 + (p & 3);
            float denom = 1.f;
            if ((unsigned)r2 < (unsigned)HB && (unsigned)c2 < (unsigned)WB)
                denom = g_S[(size_t)(b * HEADS + h2) * NPIX + r2 * WB + c2];
            wgt = ex / denom;
        }
        s_wgt[pg][slot * 8 + h] = wgt;
        if (h == 0) s_win[pg][slot] = w;
    }
    __syncthreads();

    const int h = j >> 3;
    float4 out = make_float4(0.f, 0.f, 0.f, 0.f);
#pragma unroll
    for (int slot = 0; slot < 4; slot++) {
        const float wgt = s_wgt[pg][slot * 8 + h];
        const int   w   = s_win[pg][slot];
        const float4 v = *(const float4*)(KV + (size_t)(b * NWIN + w) * KVD + DIM + j * 4);
        out.x = fmaf(wgt, v.x, out.x);
        out.y = fmaf(wgt, v.y, out.y);
        out.z = fmaf(wgt, v.z, out.z);
        out.w = fmaf(wgt, v.w, out.w);
    }

    float xs[4] = {out.x, out.y, out.z, out.w};
    unsigned short hb[4], lb[4];
#pragma unroll
    for (int k = 0; k < 4; k++) {
        __nv_bfloat16 hi = __float2bfloat16(xs[k]);
        __nv_bfloat16 lo = __float2bfloat16(xs[k] - __bfloat162float(hi));
        hb[k] = __bfloat16_as_ushort(hi);
        lb[k] = __bfloat16_as_ushort(lo);
    }
    const size_t idx = ((size_t)pix * DIM + j * 4) / 4;
    ((ushort4*)Phi)[idx] = make_ushort4(hb[0], hb[1], hb[2], hb[3]);
    ((ushort4*)Plo)[idx] = make_ushort4(lb[0], lb[1], lb[2], lb[3]);
}

// ---------------------------------------------------------------------------
// Launch
// ---------------------------------------------------------------------------
extern "C" void kernel_launch(void* const* d_in, const int* in_sizes, int n_in,
                              void* d_out, int out_size)
{
    (void)in_sizes; (void)n_in; (void)out_size;
    const float* Xt       = (const float*)d_in[0];
    const float* Xb       = (const float*)d_in[1];
    const float* q_w      = (const float*)d_in[2];
    const float* kv_w     = (const float*)d_in[3];
    const float* proj_w   = (const float*)d_in[4];
    const float* proj_b   = (const float*)d_in[5];
    const float* rel_init = (const float*)d_in[6];
    const float* rel_bias = (const float*)d_in[7];
    float* out = (float*)d_out;

    float *Qb, *KVb;
    __nv_bfloat16 *Xbh, *Xbl, *Xth, *Xtl, *Ph, *Pl;
    __nv_bfloat16 *wqh, *wql, *wkh, *wkl, *wph, *wpl;
    cudaGetSymbolAddress((void**)&Qb,  g_Q);
    cudaGetSymbolAddress((void**)&KVb, g_KV);
    cudaGetSymbolAddress((void**)&Xbh, g_Xbh);
    cudaGetSymbolAddress((void**)&Xbl, g_Xbl);
    cudaGetSymbolAddress((void**)&Xth, g_Xth);
    cudaGetSymbolAddress((void**)&Xtl, g_Xtl);
    cudaGetSymbolAddress((void**)&Ph,  g_Ph);
    cudaGetSymbolAddress((void**)&Pl,  g_Pl);
    cudaGetSymbolAddress((void**)&wqh, g_wqh);
    cudaGetSymbolAddress((void**)&wql, g_wql);
    cudaGetSymbolAddress((void**)&wkh, g_wkh);
    cudaGetSymbolAddress((void**)&wkl, g_wkl);
    cudaGetSymbolAddress((void**)&wph, g_wph);
    cudaGetSymbolAddress((void**)&wpl, g_wpl);

    cudaFuncSetAttribute(gemm_qkv,
                         cudaFuncAttributeMaxDynamicSharedMemorySize, GEMM_SMEM);
    cudaFuncSetAttribute(gemm_proj,
                         cudaFuncAttributeMaxDynamicSharedMemorySize, GEMM_SMEM);

    // fused splits
    split_all<<<(S4 / 2 + 255) / 256, 256>>>(Xb, Xt, q_w, kv_w, proj_w,
                                             Xbh, Xbl, Xth, Xtl,
                                             wqh, wql, wkh, wkl, wph, wpl);

    // 1+2) Q = Xb @ q_w^T and KV = Xt @ kv_w^T in one launch (single tail)
    gemm_qkv<<<QBLKS + KVBLKS, 128, GEMM_SMEM>>>(
        Xbh, Xbl, wqh, wql, Xth, Xtl, wkh, wkl, Qb, KVb);

    // 3) attention numerators + sums (warp per pixel)
    attn_phase1<<<(BATCH * NPIX) / 8, 256>>>(Qb, KVb, rel_init, rel_bias);

    // 4) normalization + V + fold (writes split P)
    attn_phase2<<<(BATCH * NPIX) / 4, 256>>>(KVb, Ph, Pl);

    // 5) Out = P @ proj_w^T + proj_b
    gemm_proj<<<dim3(DIM / TBN, (BATCH * NPIX) / TBM), 128, GEMM_SMEM>>>(
        Ph, Pl, wph, wpl, proj_b, out);
}

// round 10
// speedup vs baseline: 3.3567x; 1.0231x over previous
#include <cuda_runtime.h>
#include <cuda_bf16.h>
#include <cstdint>

// ---------------------------------------------------------------------------
// Problem constants
// ---------------------------------------------------------------------------
#define HEADS 8
#define DIM   256
#define KVD   512
#define HB    128
#define WB    128
#define HT    64
#define WT    64
#define NPIX  16384
#define NWIN  4096
#define BATCH 4
#define ATT_SCALE 0.17677669529663687f

// ---------------------------------------------------------------------------
// Scratch (device globals)
// ---------------------------------------------------------------------------
__device__ float g_Q [BATCH * NPIX * DIM];
__device__ float g_KV[BATCH * NWIN * KVD];
__device__ float g_E [BATCH * NWIN * HEADS * 16];
__device__ float g_S [BATCH * HEADS * NPIX];

__device__ __nv_bfloat16 g_Xbh[BATCH * NPIX * DIM];
__device__ __nv_bfloat16 g_Xbl[BATCH * NPIX * DIM];
__device__ __nv_bfloat16 g_Xth[BATCH * NWIN * KVD];
__device__ __nv_bfloat16 g_Xtl[BATCH * NWIN * KVD];
__device__ __nv_bfloat16 g_Ph [BATCH * NPIX * DIM];
__device__ __nv_bfloat16 g_Pl [BATCH * NPIX * DIM];
__device__ __nv_bfloat16 g_wqh[DIM * DIM],  g_wql[DIM * DIM];
__device__ __nv_bfloat16 g_wkh[KVD * KVD],  g_wkl[KVD * KVD];
__device__ __nv_bfloat16 g_wph[DIM * DIM],  g_wpl[DIM * DIM];

// ---------------------------------------------------------------------------
// Helpers
// ---------------------------------------------------------------------------
__device__ __forceinline__ uint32_t smem_u32(const void* p) {
    uint32_t a;
    asm("{ .reg .u64 t; cvta.to.shared.u64 t, %1; cvt.u32.u64 %0, t; }"
        : "=r"(a) : "l"(p));
    return a;
}
__device__ __forceinline__ void cpasync16(uint32_t s, const void* g) {
    asm volatile("cp.async.cg.shared.global [%0], [%1], 16;" :: "r"(s), "l"(g));
}
__device__ __forceinline__ void ldm_x4(uint32_t* r, uint32_t addr) {
    asm volatile("ldmatrix.sync.aligned.m8n8.x4.shared.b16 {%0,%1,%2,%3}, [%4];"
                 : "=r"(r[0]), "=r"(r[1]), "=r"(r[2]), "=r"(r[3]) : "r"(addr));
}
__device__ __forceinline__ void mma16816(float* c, const uint32_t* a, const uint32_t* b) {
    asm volatile("mma.sync.aligned.m16n8k16.row.col.f32.bf16.bf16.f32 "
                 "{%0,%1,%2,%3}, {%4,%5,%6,%7}, {%8,%9}, {%0,%1,%2,%3};"
                 : "+f"(c[0]), "+f"(c[1]), "+f"(c[2]), "+f"(c[3])
                 : "r"(a[0]), "r"(a[1]), "r"(a[2]), "r"(a[3]),
                   "r"(b[0]), "r"(b[1]));
}
// swizzled byte offset of (row r, 16B-chunk c) inside a [128 x 64B] tile
__device__ __forceinline__ uint32_t sw_off(int r, int c) {
    return (uint32_t)(r * 64 + ((c ^ ((r >> 1) & 3)) << 4));
}

// ---------------------------------------------------------------------------
// Fused split: all five fp32 -> (hi,lo) bf16 conversions, 2 float4/thread.
// ---------------------------------------------------------------------------
#define S0 (BATCH * NPIX * DIM / 4)
#define S1 (S0 + BATCH * NWIN * KVD / 4)
#define S2 (S1 + DIM * DIM / 4)
#define S3 (S2 + KVD * KVD / 4)
#define S4 (S3 + DIM * DIM / 4)

__device__ __forceinline__ void split_one(int i,
    const float* Xb, const float* Xt, const float* qw, const float* kw,
    const float* pw,
    __nv_bfloat16* Xbh, __nv_bfloat16* Xbl, __nv_bfloat16* Xth, __nv_bfloat16* Xtl,
    __nv_bfloat16* wqh, __nv_bfloat16* wql, __nv_bfloat16* wkh, __nv_bfloat16* wkl,
    __nv_bfloat16* wph, __nv_bfloat16* wpl)
{
    const float* src; __nv_bfloat16 *ph, *pl; int base;
    if (i < S0)      { src = Xb; ph = Xbh; pl = Xbl; base = 0;  }
    else if (i < S1) { src = Xt; ph = Xth; pl = Xtl; base = S0; }
    else if (i < S2) { src = qw; ph = wqh; pl = wql; base = S1; }
    else if (i < S3) { src = kw; ph = wkh; pl = wkl; base = S2; }
    else             { src = pw; ph = wph; pl = wpl; base = S3; }
    const int k = i - base;
    float4 v = ((const float4*)src)[k];
    float xs[4] = {v.x, v.y, v.z, v.w};
    unsigned short hb[4], lb[4];
#pragma unroll
    for (int q = 0; q < 4; q++) {
        __nv_bfloat16 h = __float2bfloat16(xs[q]);
        __nv_bfloat16 l = __float2bfloat16(xs[q] - __bfloat162float(h));
        hb[q] = __bfloat16_as_ushort(h);
        lb[q] = __bfloat16_as_ushort(l);
    }
    ((ushort4*)ph)[k] = make_ushort4(hb[0], hb[1], hb[2], hb[3]);
    ((ushort4*)pl)[k] = make_ushort4(lb[0], lb[1], lb[2], lb[3]);
}

__global__ __launch_bounds__(256)
void split_all(const float* __restrict__ Xb, const float* __restrict__ Xt,
               const float* __restrict__ qw, const float* __restrict__ kw,
               const float* __restrict__ pw,
               __nv_bfloat16* __restrict__ Xbh, __nv_bfloat16* __restrict__ Xbl,
               __nv_bfloat16* __restrict__ Xth, __nv_bfloat16* __restrict__ Xtl,
               __nv_bfloat16* __restrict__ wqh, __nv_bfloat16* __restrict__ wql,
               __nv_bfloat16* __restrict__ wkh, __nv_bfloat16* __restrict__ wkl,
               __nv_bfloat16* __restrict__ wph, __nv_bfloat16* __restrict__ wpl)
{
    int i0 = (blockIdx.x * blockDim.x + threadIdx.x) * 2;
    if (i0 < S4)
        split_one(i0, Xb, Xt, qw, kw, pw, Xbh, Xbl, Xth, Xtl,
                  wqh, wql, wkh, wkl, wph, wpl);
    if (i0 + 1 < S4)
        split_one(i0 + 1, Xb, Xt, qw, kw, pw, Xbh, Xbl, Xth, Xtl,
                  wqh, wql, wkh, wkl, wph, wpl);
}

// ---------------------------------------------------------------------------
// HMMA split-bf16 GEMM body: C[m,n] = sum_k A[m,k]*B[n,k] (+bias[n]).
// 3 products: Ah*Bh + Ah*Bl + Al*Bh. Tile 128x128, BK=32, 4 warps (64x64
// warp tile), 3-stage cp.async pipeline, one barrier per chunk, 2 CTAs/SM.
// ---------------------------------------------------------------------------
#define TBM 128
#define TBN 128
#define TBK 32
#define TILE_B   8192                 // one [128 x 64B] tile
#define STAGE_B  (4 * TILE_B)        // Ah | Al | Bh | Bl
#define NSTAGE   3
#define GEMM_SMEM (NSTAGE * STAGE_B) // 96 KB

__device__ __forceinline__ void gemm_body(
    const __nv_bfloat16* __restrict__ Ahi, const __nv_bfloat16* __restrict__ Alo,
    const __nv_bfloat16* __restrict__ Bhi, const __nv_bfloat16* __restrict__ Blo,
    const float* __restrict__ bias, float* __restrict__ C,
    int N, int K, int bm, int bn, char* dsm)
{
    const uint32_t sbase = smem_u32(dsm);
    const int tid  = threadIdx.x;
    const int wid  = tid >> 5;
    const int lane = tid & 31;
    const int wm   = wid & 1;        // 2 warps along M (64 rows each)
    const int wn   = wid >> 1;       // 2 warps along N (64 cols each)
    const int KC   = K / TBK;

    float acc[4][8][4];
#pragma unroll
    for (int mi = 0; mi < 4; mi++)
#pragma unroll
        for (int ni = 0; ni < 8; ni++)
#pragma unroll
            for (int q = 0; q < 4; q++) acc[mi][ni][q] = 0.f;

    auto load_chunk = [&](int ch, int stage) {
        const int k0 = ch * TBK;
        const uint32_t st = sbase + stage * STAGE_B;
#pragma unroll
        for (int t2 = 0; t2 < 4; t2++) {
            const int id = tid + t2 * 128;   // 0..511
            const int r  = id >> 2;
            const int c  = id & 3;
            const uint32_t off = sw_off(r, c);
            const size_t ga = (size_t)(bm + r) * K + k0 + c * 8;
            const size_t gb = (size_t)(bn + r) * K + k0 + c * 8;
            cpasync16(st + 0 * TILE_B + off, Ahi + ga);
            cpasync16(st + 1 * TILE_B + off, Alo + ga);
            cpasync16(st + 2 * TILE_B + off, Bhi + gb);
            cpasync16(st + 3 * TILE_B + off, Blo + gb);
        }
        asm volatile("cp.async.commit_group;" ::: "memory");
    };

    load_chunk(0, 0);
    load_chunk(1, 1);

    for (int ch = 0; ch < KC; ch++) {
        asm volatile("cp.async.wait_group 1;" ::: "memory");  // chunk ch resident
        __syncthreads();                                      // all warps done with ch-1
        if (ch + 2 < KC) load_chunk(ch + 2, (ch + 2) % NSTAGE);
        else asm volatile("cp.async.commit_group;" ::: "memory");

        const uint32_t st = sbase + (ch % NSTAGE) * STAGE_B;
#pragma unroll
        for (int ks = 0; ks < 2; ks++) {
            uint32_t ah[4][4], al[4][4];
#pragma unroll
            for (int mi = 0; mi < 4; mi++) {
                const int r = wm * 64 + mi * 16 + ((lane >> 3) & 1) * 8 + (lane & 7);
                const int c = ks * 2 + (lane >> 4);
                const uint32_t off = sw_off(r, c);
                ldm_x4(ah[mi], st + 0 * TILE_B + off);
                ldm_x4(al[mi], st + 1 * TILE_B + off);
            }
#pragma unroll
            for (int g = 0; g < 4; g++) {
                const int r = wn * 64 + g * 16 + ((lane >> 4) & 1) * 8 + (lane & 7);
                const int c = ks * 2 + ((lane >> 3) & 1);
                const uint32_t off = sw_off(r, c);
                uint32_t th[4], tl[4];
                ldm_x4(th, st + 2 * TILE_B + off);
                ldm_x4(tl, st + 3 * TILE_B + off);
#pragma unroll
                for (int mi = 0; mi < 4; mi++) {
                    mma16816(acc[mi][2 * g],     ah[mi], th);
                    mma16816(acc[mi][2 * g],     ah[mi], tl);
                    mma16816(acc[mi][2 * g],     al[mi], th);
                    mma16816(acc[mi][2 * g + 1], ah[mi], th + 2);
                    mma16816(acc[mi][2 * g + 1], ah[mi], tl + 2);
                    mma16816(acc[mi][2 * g + 1], al[mi], th + 2);
                }
            }
        }
    }

    const int rbase = bm + wm * 64 + (lane >> 2);
    const int cbase = bn + wn * 64 + (lane & 3) * 2;
#pragma unroll
    for (int mi = 0; mi < 4; mi++) {
#pragma unroll
        for (int ni = 0; ni < 8; ni++) {
            const int col = cbase + ni * 8;
            float b0 = 0.f, b1 = 0.f;
            if (bias) { b0 = __ldg(bias + col); b1 = __ldg(bias + col + 1); }
            float* p0 = C + (size_t)(rbase + mi * 16) * N + col;
            float* p1 = C + (size_t)(rbase + mi * 16 + 8) * N + col;
            *(float2*)p0 = make_float2(acc[mi][ni][0] + b0, acc[mi][ni][1] + b1);
            *(float2*)p1 = make_float2(acc[mi][ni][2] + b0, acc[mi][ni][3] + b1);
        }
    }
}

// Fused KV-GEMM (long tiles FIRST, LPT scheduling) + Q-GEMM (short tiles
// drain the tail).
#define QBLKS  ((BATCH * NPIX / TBM) * (DIM / TBN))   // 512*2 = 1024
#define KVBLKS ((BATCH * NWIN / TBM) * (KVD / TBN))   // 128*4 = 512

__global__ __launch_bounds__(128, 2)
void gemm_qkv(const __nv_bfloat16* __restrict__ Xbh, const __nv_bfloat16* __restrict__ Xbl,
              const __nv_bfloat16* __restrict__ wqh, const __nv_bfloat16* __restrict__ wql,
              const __nv_bfloat16* __restrict__ Xth, const __nv_bfloat16* __restrict__ Xtl,
              const __nv_bfloat16* __restrict__ wkh, const __nv_bfloat16* __restrict__ wkl,
              float* __restrict__ Q, float* __restrict__ KV)
{
    extern __shared__ char dsm[];
    const int bid = blockIdx.x;
    if (bid < KVBLKS) {
        gemm_body(Xth, Xtl, wkh, wkl, nullptr, KV,
                  KVD, KVD, (bid >> 2) * TBM, (bid & 3) * TBN, dsm);
    } else {
        const int t = bid - KVBLKS;
        gemm_body(Xbh, Xbl, wqh, wql, nullptr, Q,
                  DIM, DIM, (t >> 1) * TBM, (t & 1) * TBN, dsm);
    }
}

__global__ __launch_bounds__(128, 2)
void gemm_proj(const __nv_bfloat16* __restrict__ Ph, const __nv_bfloat16* __restrict__ Pl,
               const __nv_bfloat16* __restrict__ wph, const __nv_bfloat16* __restrict__ wpl,
               const float* __restrict__ bias, float* __restrict__ C)
{
    extern __shared__ char dsm[];
    gemm_body(Ph, Pl, wph, wpl, bias, C,
              DIM, DIM, (int)blockIdx.y * TBM, (int)blockIdx.x * TBN, dsm);
}

// ---------------------------------------------------------------------------
// Covering-window enumeration
// ---------------------------------------------------------------------------
__device__ __forceinline__ int covers(int r, int lim, int tys[2], int iis[2])
{
    const int th = (r + 1) >> 1;
    const int ih = (r + 1) & 1;
    int n = 0;
    if (th < lim) { tys[n] = th;     iis[n] = ih;     n++; }
    if (th >= 1)  { tys[n] = th - 1; iis[n] = ih + 2; n++; }
    return n;
}

// ---------------------------------------------------------------------------
// Phase 1 (warp per pixel): exp(logits) -> g_E, per-(head,pixel) sums -> g_S.
// Lane: head = lane>>2, 4 lanes per head, 8 channels per lane. 32-bit offsets.
// ---------------------------------------------------------------------------
__global__ __launch_bounds__(256)
void attn_phase1(const float* __restrict__ Q, const float* __restrict__ KV,
                 const float* __restrict__ rel_init,
                 const float* __restrict__ rel_bias)
{
    __shared__ float s_rel[16];
    if (threadIdx.x < 16)
        s_rel[threadIdx.x] = rel_init[threadIdx.x] + rel_bias[threadIdx.x];
    __syncthreads();

    const int wrp  = threadIdx.x >> 5;
    const int lane = threadIdx.x & 31;
    const int pix  = blockIdx.x * 8 + wrp;
    const int b    = pix >> 14;
    const int rc   = pix & (NPIX - 1);
    const int r    = rc >> 7;
    const int c    = rc & (WB - 1);
    const int h    = lane >> 2;
    const int l4   = lane & 3;
    const int ch   = h * 32 + l4 * 8;

    const float* qp = Q + (size_t)pix * DIM + ch;
    const float4 q0 = *(const float4*)qp;
    const float4 q1 = *(const float4*)(qp + 4);
    const float* kvbase = KV + (size_t)b * (NWIN * KVD) + ch;   // + w*KVD per window

    int tys[2], iis[2], txs[2], jjs[2];
    const int nty = covers(r, HT, tys, iis);
    const int ntx = covers(c, WT, txs, jjs);

    float ssum = 0.f;
#pragma unroll
    for (int a = 0; a < 2; a++) {
        if (a >= nty) break;
#pragma unroll
        for (int e = 0; e < 2; e++) {
            if (e >= ntx) break;
            const int w = tys[a] * WT + txs[e];
            const int p = iis[a] * 4 + jjs[e];
            const float* kp = kvbase + w * KVD;          // 32-bit offset
            const float4 k0 = *(const float4*)kp;
            const float4 k1 = *(const float4*)(kp + 4);
            float part = q0.x * k0.x + q0.y * k0.y + q0.z * k0.z + q0.w * k0.w
                       + q1.x * k1.x + q1.y * k1.y + q1.z * k1.z + q1.w * k1.w;
            part += __shfl_xor_sync(0xffffffffu, part, 2);
            part += __shfl_xor_sync(0xffffffffu, part, 1);
            const float ex = expf(part * ATT_SCALE + s_rel[p]);
            ssum += ex;
            if (l4 == 0)
                g_E[((size_t)(b * NWIN + w) * HEADS + h) * 16 + p] = ex;
        }
    }
    if (l4 == 0)
        g_S[(size_t)(b * HEADS + h) * NPIX + rc] = ssum;
}

// ---------------------------------------------------------------------------
// Phase 2: per-(pixel,slot,head) weights + per-slot V-row offsets staged in
// smem by 32 threads; 64 threads then do pure base+offset V-FMAs; writes
// hi/lo bf16 split of P. Scrambled divisor faithful to the reference reshape.
// ---------------------------------------------------------------------------
__global__ __launch_bounds__(256)
void attn_phase2(const float* __restrict__ KV,
                 __nv_bfloat16* __restrict__ Phi, __nv_bfloat16* __restrict__ Plo)
{
    __shared__ float s_wgt[4][32];   // [pixel-in-block][slot*8 + head]
    __shared__ int   s_off[4][4];    // [pixel-in-block][slot] = w*KVD

    const int pg  = threadIdx.x >> 6;
    const int j   = threadIdx.x & 63;
    const int pix = blockIdx.x * 4 + pg;
    const int b   = pix >> 14;
    const int rc  = pix & (NPIX - 1);
    const int r   = rc >> 7;
    const int c   = rc & (WB - 1);

    if (j < 32) {
        const int slot = j >> 3;   // a*2 + e
        const int h    = j & 7;
        int tys[2], iis[2], txs[2], jjs[2];
        const int nty = covers(r, HT, tys, iis);
        const int ntx = covers(c, WT, txs, jjs);
        const int a = slot >> 1;
        const int e = slot & 1;
        float wgt = 0.f;
        int   w   = 0;
        if (a < nty && e < ntx) {
            w = tys[a] * WT + txs[e];
            const int p = iis[a] * 4 + jjs[e];
            const float ex = g_E[((size_t)(b * NWIN + w) * HEADS + h) * 16 + p];
            const int h2 = w >> 9;
            const int w2 = ((w & 511) << 3) + h;
            const int r2 = 2 * (w2 >> 6) - 1 + (p >> 2);
            const int c2 = 2 * (w2 & 63) - 1 + (p & 3);
            float denom = 1.f;
            if ((unsigned)r2 < (unsigned)HB && (unsigned)c2 < (unsigned)WB)
                denom = g_S[(size_t)(b * HEADS + h2) * NPIX + r2 * WB + c2];
            wgt = ex / denom;
        }
        s_wgt[pg][slot * 8 + h] = wgt;
        if (h == 0) s_off[pg][slot] = w * KVD;
    }
    __syncthreads();

    const int h = j >> 3;
    const float* vbase = KV + (size_t)b * (NWIN * KVD) + DIM + j * 4;
    float4 out = make_float4(0.f, 0.f, 0.f, 0.f);
#pragma unroll
    for (int slot = 0; slot < 4; slot++) {
        const float wgt = s_wgt[pg][slot * 8 + h];
        const float4 v = *(const float4*)(vbase + s_off[pg][slot]);
        out.x = fmaf(wgt, v.x, out.x);
        out.y = fmaf(wgt, v.y, out.y);
        out.z = fmaf(wgt, v.z, out.z);
        out.w = fmaf(wgt, v.w, out.w);
    }

    float xs[4] = {out.x, out.y, out.z, out.w};
    unsigned short hb[4], lb[4];
#pragma unroll
    for (int k = 0; k < 4; k++) {
        __nv_bfloat16 hi = __float2bfloat16(xs[k]);
        __nv_bfloat16 lo = __float2bfloat16(xs[k] - __bfloat162float(hi));
        hb[k] = __bfloat16_as_ushort(hi);
        lb[k] = __bfloat16_as_ushort(lo);
    }
    const size_t idx = ((size_t)pix * DIM + j * 4) / 4;
    ((ushort4*)Phi)[idx] = make_ushort4(hb[0], hb[1], hb[2], hb[3]);
    ((ushort4*)Plo)[idx] = make_ushort4(lb[0], lb[1], lb[2], lb[3]);
}

// ---------------------------------------------------------------------------
// Launch
// ---------------------------------------------------------------------------
extern "C" void kernel_launch(void* const* d_in, const int* in_sizes, int n_in,
                              void* d_out, int out_size)
{
    (void)in_sizes; (void)n_in; (void)out_size;
    const float* Xt       = (const float*)d_in[0];
    const float* Xb       = (const float*)d_in[1];
    const float* q_w      = (const float*)d_in[2];
    const float* kv_w     = (const float*)d_in[3];
    const float* proj_w   = (const float*)d_in[4];
    const float* proj_b   = (const float*)d_in[5];
    const float* rel_init = (const float*)d_in[6];
    const float* rel_bias = (const float*)d_in[7];
    float* out = (float*)d_out;

    float *Qb, *KVb;
    __nv_bfloat16 *Xbh, *Xbl, *Xth, *Xtl, *Ph, *Pl;
    __nv_bfloat16 *wqh, *wql, *wkh, *wkl, *wph, *wpl;
    cudaGetSymbolAddress((void**)&Qb,  g_Q);
    cudaGetSymbolAddress((void**)&KVb, g_KV);
    cudaGetSymbolAddress((void**)&Xbh, g_Xbh);
    cudaGetSymbolAddress((void**)&Xbl, g_Xbl);
    cudaGetSymbolAddress((void**)&Xth, g_Xth);
    cudaGetSymbolAddress((void**)&Xtl, g_Xtl);
    cudaGetSymbolAddress((void**)&Ph,  g_Ph);
    cudaGetSymbolAddress((void**)&Pl,  g_Pl);
    cudaGetSymbolAddress((void**)&wqh, g_wqh);
    cudaGetSymbolAddress((void**)&wql, g_wql);
    cudaGetSymbolAddress((void**)&wkh, g_wkh);
    cudaGetSymbolAddress((void**)&wkl, g_wkl);
    cudaGetSymbolAddress((void**)&wph, g_wph);
    cudaGetSymbolAddress((void**)&wpl, g_wpl);

    cudaFuncSetAttribute(gemm_qkv,
                         cudaFuncAttributeMaxDynamicSharedMemorySize, GEMM_SMEM);
    cudaFuncSetAttribute(gemm_proj,
                         cudaFuncAttributeMaxDynamicSharedMemorySize, GEMM_SMEM);

    // fused splits
    split_all<<<(S4 / 2 + 255) / 256, 256>>>(Xb, Xt, q_w, kv_w, proj_w,
                                             Xbh, Xbl, Xth, Xtl,
                                             wqh, wql, wkh, wkl, wph, wpl);

    // 1+2) KV = Xt @ kv_w^T (long tiles first) and Q = Xb @ q_w^T
    gemm_qkv<<<QBLKS + KVBLKS, 128, GEMM_SMEM>>>(
        Xbh, Xbl, wqh, wql, Xth, Xtl, wkh, wkl, Qb, KVb);

    // 3) attention numerators + sums (warp per pixel)
    attn_phase1<<<(BATCH * NPIX) / 8, 256>>>(Qb, KVb, rel_init, rel_bias);

    // 4) normalization + V + fold (writes split P)
    attn_phase2<<<(BATCH * NPIX) / 4, 256>>>(KVb, Ph, Pl);

    // 5) Out = P @ proj_w^T + proj_b
    gemm_proj<<<dim3(DIM / TBN, (BATCH * NPIX) / TBM), 128, GEMM_SMEM>>>(
        Ph, Pl, wph, wpl, proj_b, out);
}

// round 11
// speedup vs baseline: 3.3950x; 1.0114x over previous
#include <cuda_runtime.h>
#include <cuda_bf16.h>
#include <cstdint>

// ---------------------------------------------------------------------------
// Problem constants
// ---------------------------------------------------------------------------
#define HEADS 8
#define DIM   256
#define KVD   512
#define HB    128
#define WB    128
#define HT    64
#define WT    64
#define NPIX  16384
#define NWIN  4096
#define BATCH 4
#define ATT_SCALE 0.17677669529663687f

// ---------------------------------------------------------------------------
// Scratch (device globals)
// ---------------------------------------------------------------------------
__device__ float g_Q [BATCH * NPIX * DIM];
__device__ float g_KV[BATCH * NWIN * KVD];
__device__ float g_E [BATCH * NWIN * HEADS * 16];
__device__ float g_S [BATCH * HEADS * NPIX];

__device__ __nv_bfloat16 g_Xbh[BATCH * NPIX * DIM];
__device__ __nv_bfloat16 g_Xbl[BATCH * NPIX * DIM];
__device__ __nv_bfloat16 g_Xth[BATCH * NWIN * KVD];
__device__ __nv_bfloat16 g_Xtl[BATCH * NWIN * KVD];
__device__ __nv_bfloat16 g_Ph [BATCH * NPIX * DIM];
__device__ __nv_bfloat16 g_Pl [BATCH * NPIX * DIM];
__device__ __nv_bfloat16 g_wqh[DIM * DIM],  g_wql[DIM * DIM];
__device__ __nv_bfloat16 g_wkh[KVD * KVD],  g_wkl[KVD * KVD];
__device__ __nv_bfloat16 g_wph[DIM * DIM],  g_wpl[DIM * DIM];

// ---------------------------------------------------------------------------
// Helpers
// ---------------------------------------------------------------------------
__device__ __forceinline__ uint32_t smem_u32(const void* p) {
    uint32_t a;
    asm("{ .reg .u64 t; cvta.to.shared.u64 t, %1; cvt.u32.u64 %0, t; }"
        : "=r"(a) : "l"(p));
    return a;
}
__device__ __forceinline__ void cpasync16(uint32_t s, const void* g) {
    asm volatile("cp.async.cg.shared.global [%0], [%1], 16;" :: "r"(s), "l"(g));
}
__device__ __forceinline__ void ldm_x4(uint32_t* r, uint32_t addr) {
    asm volatile("ldmatrix.sync.aligned.m8n8.x4.shared.b16 {%0,%1,%2,%3}, [%4];"
                 : "=r"(r[0]), "=r"(r[1]), "=r"(r[2]), "=r"(r[3]) : "r"(addr));
}
__device__ __forceinline__ void mma16816(float* c, const uint32_t* a, const uint32_t* b) {
    asm volatile("mma.sync.aligned.m16n8k16.row.col.f32.bf16.bf16.f32 "
                 "{%0,%1,%2,%3}, {%4,%5,%6,%7}, {%8,%9}, {%0,%1,%2,%3};"
                 : "+f"(c[0]), "+f"(c[1]), "+f"(c[2]), "+f"(c[3])
                 : "r"(a[0]), "r"(a[1]), "r"(a[2]), "r"(a[3]),
                   "r"(b[0]), "r"(b[1]));
}
// swizzled byte offset of (row r, 16B-chunk c) inside a [128 x 64B] tile
__device__ __forceinline__ uint32_t sw_off(int r, int c) {
    return (uint32_t)(r * 64 + ((c ^ ((r >> 1) & 3)) << 4));
}

// ---------------------------------------------------------------------------
// Fused split: all five fp32 -> (hi,lo) bf16 conversions, 2 float4/thread.
// ---------------------------------------------------------------------------
#define S0 (BATCH * NPIX * DIM / 4)
#define S1 (S0 + BATCH * NWIN * KVD / 4)
#define S2 (S1 + DIM * DIM / 4)
#define S3 (S2 + KVD * KVD / 4)
#define S4 (S3 + DIM * DIM / 4)

__device__ __forceinline__ void split_one(int i,
    const float* Xb, const float* Xt, const float* qw, const float* kw,
    const float* pw,
    __nv_bfloat16* Xbh, __nv_bfloat16* Xbl, __nv_bfloat16* Xth, __nv_bfloat16* Xtl,
    __nv_bfloat16* wqh, __nv_bfloat16* wql, __nv_bfloat16* wkh, __nv_bfloat16* wkl,
    __nv_bfloat16* wph, __nv_bfloat16* wpl)
{
    const float* src; __nv_bfloat16 *ph, *pl; int base;
    if (i < S0)      { src = Xb; ph = Xbh; pl = Xbl; base = 0;  }
    else if (i < S1) { src = Xt; ph = Xth; pl = Xtl; base = S0; }
    else if (i < S2) { src = qw; ph = wqh; pl = wql; base = S1; }
    else if (i < S3) { src = kw; ph = wkh; pl = wkl; base = S2; }
    else             { src = pw; ph = wph; pl = wpl; base = S3; }
    const int k = i - base;
    float4 v = ((const float4*)src)[k];
    float xs[4] = {v.x, v.y, v.z, v.w};
    unsigned short hb[4], lb[4];
#pragma unroll
    for (int q = 0; q < 4; q++) {
        __nv_bfloat16 h = __float2bfloat16(xs[q]);
        __nv_bfloat16 l = __float2bfloat16(xs[q] - __bfloat162float(h));
        hb[q] = __bfloat16_as_ushort(h);
        lb[q] = __bfloat16_as_ushort(l);
    }
    ((ushort4*)ph)[k] = make_ushort4(hb[0], hb[1], hb[2], hb[3]);
    ((ushort4*)pl)[k] = make_ushort4(lb[0], lb[1], lb[2], lb[3]);
}

__global__ __launch_bounds__(256)
void split_all(const float* __restrict__ Xb, const float* __restrict__ Xt,
               const float* __restrict__ qw, const float* __restrict__ kw,
               const float* __restrict__ pw,
               __nv_bfloat16* __restrict__ Xbh, __nv_bfloat16* __restrict__ Xbl,
               __nv_bfloat16* __restrict__ Xth, __nv_bfloat16* __restrict__ Xtl,
               __nv_bfloat16* __restrict__ wqh, __nv_bfloat16* __restrict__ wql,
               __nv_bfloat16* __restrict__ wkh, __nv_bfloat16* __restrict__ wkl,
               __nv_bfloat16* __restrict__ wph, __nv_bfloat16* __restrict__ wpl)
{
    int i0 = (blockIdx.x * blockDim.x + threadIdx.x) * 2;
    if (i0 < S4)
        split_one(i0, Xb, Xt, qw, kw, pw, Xbh, Xbl, Xth, Xtl,
                  wqh, wql, wkh, wkl, wph, wpl);
    if (i0 + 1 < S4)
        split_one(i0 + 1, Xb, Xt, qw, kw, pw, Xbh, Xbl, Xth, Xtl,
                  wqh, wql, wkh, wkl, wph, wpl);
}

// ---------------------------------------------------------------------------
// HMMA split-bf16 GEMM body: C[m,n] = sum_k A[m,k]*B[n,k] (+bias[n]).
// 3 products: Ah*Bh + Ah*Bl + Al*Bh. Tile 128x128, BK=32, 4 warps (64x64
// warp tile), 3-stage cp.async pipeline, one barrier per chunk, 2 CTAs/SM.
// ---------------------------------------------------------------------------
#define TBM 128
#define TBN 128
#define TBK 32
#define TILE_B   8192                 // one [128 x 64B] tile
#define STAGE_B  (4 * TILE_B)        // Ah | Al | Bh | Bl
#define NSTAGE   3
#define GEMM_SMEM (NSTAGE * STAGE_B) // 96 KB

__device__ __forceinline__ void gemm_body(
    const __nv_bfloat16* __restrict__ Ahi, const __nv_bfloat16* __restrict__ Alo,
    const __nv_bfloat16* __restrict__ Bhi, const __nv_bfloat16* __restrict__ Blo,
    const float* __restrict__ bias, float* __restrict__ C,
    int N, int K, int bm, int bn, char* dsm)
{
    const uint32_t sbase = smem_u32(dsm);
    const int tid  = threadIdx.x;
    const int wid  = tid >> 5;
    const int lane = tid & 31;
    const int wm   = wid & 1;        // 2 warps along M (64 rows each)
    const int wn   = wid >> 1;       // 2 warps along N (64 cols each)
    const int KC   = K / TBK;

    float acc[4][8][4];
#pragma unroll
    for (int mi = 0; mi < 4; mi++)
#pragma unroll
        for (int ni = 0; ni < 8; ni++)
#pragma unroll
            for (int q = 0; q < 4; q++) acc[mi][ni][q] = 0.f;

    auto load_chunk = [&](int ch, int stage) {
        const int k0 = ch * TBK;
        const uint32_t st = sbase + stage * STAGE_B;
#pragma unroll
        for (int t2 = 0; t2 < 4; t2++) {
            const int id = tid + t2 * 128;   // 0..511
            const int r  = id >> 2;
            const int c  = id & 3;
            const uint32_t off = sw_off(r, c);
            const size_t ga = (size_t)(bm + r) * K + k0 + c * 8;
            const size_t gb = (size_t)(bn + r) * K + k0 + c * 8;
            cpasync16(st + 0 * TILE_B + off, Ahi + ga);
            cpasync16(st + 1 * TILE_B + off, Alo + ga);
            cpasync16(st + 2 * TILE_B + off, Bhi + gb);
            cpasync16(st + 3 * TILE_B + off, Blo + gb);
        }
        asm volatile("cp.async.commit_group;" ::: "memory");
    };

    load_chunk(0, 0);
    load_chunk(1, 1);

    for (int ch = 0; ch < KC; ch++) {
        asm volatile("cp.async.wait_group 1;" ::: "memory");  // chunk ch resident
        __syncthreads();                                      // all warps done with ch-1
        if (ch + 2 < KC) load_chunk(ch + 2, (ch + 2) % NSTAGE);
        else asm volatile("cp.async.commit_group;" ::: "memory");

        const uint32_t st = sbase + (ch % NSTAGE) * STAGE_B;
#pragma unroll
        for (int ks = 0; ks < 2; ks++) {
            uint32_t ah[4][4], al[4][4];
#pragma unroll
            for (int mi = 0; mi < 4; mi++) {
                const int r = wm * 64 + mi * 16 + ((lane >> 3) & 1) * 8 + (lane & 7);
                const int c = ks * 2 + (lane >> 4);
                const uint32_t off = sw_off(r, c);
                ldm_x4(ah[mi], st + 0 * TILE_B + off);
                ldm_x4(al[mi], st + 1 * TILE_B + off);
            }
#pragma unroll
            for (int g = 0; g < 4; g++) {
                const int r = wn * 64 + g * 16 + ((lane >> 4) & 1) * 8 + (lane & 7);
                const int c = ks * 2 + ((lane >> 3) & 1);
                const uint32_t off = sw_off(r, c);
                uint32_t th[4], tl[4];
                ldm_x4(th, st + 2 * TILE_B + off);
                ldm_x4(tl, st + 3 * TILE_B + off);
#pragma unroll
                for (int mi = 0; mi < 4; mi++) {
                    mma16816(acc[mi][2 * g],     ah[mi], th);
                    mma16816(acc[mi][2 * g],     ah[mi], tl);
                    mma16816(acc[mi][2 * g],     al[mi], th);
                    mma16816(acc[mi][2 * g + 1], ah[mi], th + 2);
                    mma16816(acc[mi][2 * g + 1], ah[mi], tl + 2);
                    mma16816(acc[mi][2 * g + 1], al[mi], th + 2);
                }
            }
        }
    }

    const int rbase = bm + wm * 64 + (lane >> 2);
    const int cbase = bn + wn * 64 + (lane & 3) * 2;
#pragma unroll
    for (int mi = 0; mi < 4; mi++) {
#pragma unroll
        for (int ni = 0; ni < 8; ni++) {
            const int col = cbase + ni * 8;
            float b0 = 0.f, b1 = 0.f;
            if (bias) { b0 = __ldg(bias + col); b1 = __ldg(bias + col + 1); }
            float* p0 = C + (size_t)(rbase + mi * 16) * N + col;
            float* p1 = C + (size_t)(rbase + mi * 16 + 8) * N + col;
            *(float2*)p0 = make_float2(acc[mi][ni][0] + b0, acc[mi][ni][1] + b1);
            *(float2*)p1 = make_float2(acc[mi][ni][2] + b0, acc[mi][ni][3] + b1);
        }
    }
}

// Fused KV-GEMM (long tiles FIRST, LPT scheduling) + Q-GEMM (short tiles
// drain the tail).
#define QBLKS  ((BATCH * NPIX / TBM) * (DIM / TBN))   // 1024
#define KVBLKS ((BATCH * NWIN / TBM) * (KVD / TBN))   // 512

__global__ __launch_bounds__(128, 2)
void gemm_qkv(const __nv_bfloat16* __restrict__ Xbh, const __nv_bfloat16* __restrict__ Xbl,
              const __nv_bfloat16* __restrict__ wqh, const __nv_bfloat16* __restrict__ wql,
              const __nv_bfloat16* __restrict__ Xth, const __nv_bfloat16* __restrict__ Xtl,
              const __nv_bfloat16* __restrict__ wkh, const __nv_bfloat16* __restrict__ wkl,
              float* __restrict__ Q, float* __restrict__ KV)
{
    extern __shared__ char dsm[];
    const int bid = blockIdx.x;
    if (bid < KVBLKS) {
        gemm_body(Xth, Xtl, wkh, wkl, nullptr, KV,
                  KVD, KVD, (bid >> 2) * TBM, (bid & 3) * TBN, dsm);
    } else {
        const int t = bid - KVBLKS;
        gemm_body(Xbh, Xbl, wqh, wql, nullptr, Q,
                  DIM, DIM, (t >> 1) * TBM, (t & 1) * TBN, dsm);
    }
}

__global__ __launch_bounds__(128, 2)
void gemm_proj(const __nv_bfloat16* __restrict__ Ph, const __nv_bfloat16* __restrict__ Pl,
               const __nv_bfloat16* __restrict__ wph, const __nv_bfloat16* __restrict__ wpl,
               const float* __restrict__ bias, float* __restrict__ C)
{
    extern __shared__ char dsm[];
    gemm_body(Ph, Pl, wph, wpl, bias, C,
              DIM, DIM, (int)blockIdx.y * TBM, (int)blockIdx.x * TBN, dsm);
}

// ---------------------------------------------------------------------------
// Covering-window enumeration
// ---------------------------------------------------------------------------
__device__ __forceinline__ int covers(int r, int lim, int tys[2], int iis[2])
{
    const int th = (r + 1) >> 1;
    const int ih = (r + 1) & 1;
    int n = 0;
    if (th < lim) { tys[n] = th;     iis[n] = ih;     n++; }
    if (th >= 1)  { tys[n] = th - 1; iis[n] = ih + 2; n++; }
    return n;
}

// ---------------------------------------------------------------------------
// Phase 1 (warp per pixel): exp(logits) -> g_E, per-(head,pixel) sums -> g_S.
// Lane: head = lane>>2, 4 lanes per head, 8 channels per lane. 32-bit offsets.
// ---------------------------------------------------------------------------
__global__ __launch_bounds__(256)
void attn_phase1(const float* __restrict__ Q, const float* __restrict__ KV,
                 const float* __restrict__ rel_init,
                 const float* __restrict__ rel_bias)
{
    __shared__ float s_rel[16];
    if (threadIdx.x < 16)
        s_rel[threadIdx.x] = rel_init[threadIdx.x] + rel_bias[threadIdx.x];
    __syncthreads();

    const int wrp  = threadIdx.x >> 5;
    const int lane = threadIdx.x & 31;
    const int pix  = blockIdx.x * 8 + wrp;
    const int b    = pix >> 14;
    const int rc   = pix & (NPIX - 1);
    const int r    = rc >> 7;
    const int c    = rc & (WB - 1);
    const int h    = lane >> 2;
    const int l4   = lane & 3;
    const int ch   = h * 32 + l4 * 8;

    const float* qp = Q + (uint32_t)pix * DIM + ch;
    const float4 q0 = *(const float4*)qp;
    const float4 q1 = *(const float4*)(qp + 4);
    const float* kvbase = KV + (uint32_t)b * (NWIN * KVD) + ch;

    int tys[2], iis[2], txs[2], jjs[2];
    const int nty = covers(r, HT, tys, iis);
    const int ntx = covers(c, WT, txs, jjs);

    float ssum = 0.f;
#pragma unroll
    for (int a = 0; a < 2; a++) {
        if (a >= nty) break;
#pragma unroll
        for (int e = 0; e < 2; e++) {
            if (e >= ntx) break;
            const int w = tys[a] * WT + txs[e];
            const int p = iis[a] * 4 + jjs[e];
            const float* kp = kvbase + w * KVD;
            const float4 k0 = *(const float4*)kp;
            const float4 k1 = *(const float4*)(kp + 4);
            float part = q0.x * k0.x + q0.y * k0.y + q0.z * k0.z + q0.w * k0.w
                       + q1.x * k1.x + q1.y * k1.y + q1.z * k1.z + q1.w * k1.w;
            part += __shfl_xor_sync(0xffffffffu, part, 2);
            part += __shfl_xor_sync(0xffffffffu, part, 1);
            const float ex = expf(part * ATT_SCALE + s_rel[p]);
            ssum += ex;
            if (l4 == 0)
                g_E[(uint32_t)((b * NWIN + w) * HEADS + h) * 16 + p] = ex;
        }
    }
    if (l4 == 0)
        g_S[(uint32_t)(b * HEADS + h) * NPIX + rc] = ssum;
}

// ---------------------------------------------------------------------------
// Phase 2 (warp per pixel, NO smem, NO barrier): lane computes one
// (slot,head) weight (32 combos = 32 lanes), shfl-exchange, then each lane
// folds 8 channels (2x float4) of V per slot. 32-bit indices throughout.
// Scrambled divisor faithful to the reference reshape. OOB slots -> wgt=0.
// ---------------------------------------------------------------------------
__global__ __launch_bounds__(256)
void attn_phase2(const float* __restrict__ KV,
                 __nv_bfloat16* __restrict__ Phi, __nv_bfloat16* __restrict__ Plo)
{
    const int wrp  = threadIdx.x >> 5;
    const int lane = threadIdx.x & 31;
    const int pix  = blockIdx.x * 8 + wrp;
    const int b    = pix >> 14;
    const int rc   = pix & (NPIX - 1);
    const int r    = rc >> 7;
    const int c    = rc & (WB - 1);

    // --- stage: this lane's (slot, head) weight ---
    int tys[2], iis[2], txs[2], jjs[2];
    const int nty = covers(r, HT, tys, iis);
    const int ntx = covers(c, WT, txs, jjs);

    const int slot = lane >> 3;    // 0..3 = a*2 + e
    const int sh   = lane & 7;     // head for staging
    const int sa   = slot >> 1;
    const int se   = slot & 1;
    float wgt = 0.f;
    int   wofs = 0;                // w*KVD
    if (sa < nty && se < ntx) {
        const int w = tys[sa] * WT + txs[se];
        const int p = iis[sa] * 4 + jjs[se];
        const float ex = g_E[(uint32_t)((b * NWIN + w) * HEADS + sh) * 16 + p];
        const int h2 = w >> 9;
        const int w2 = ((w & 511) << 3) + sh;
        const int r2 = 2 * (w2 >> 6) - 1 + (p >> 2);
        const int c2 = 2 * (w2 & 63) - 1 + (p & 3);
        float denom = 1.f;
        if ((unsigned)r2 < (unsigned)HB && (unsigned)c2 < (unsigned)WB)
            denom = g_S[(uint32_t)(b * HEADS + h2) * NPIX + r2 * WB + c2];
        wgt = ex / denom;
        wofs = w * KVD;
    }

    // --- exchange: lane needs wgt(s, my_h) and wofs(s) for s=0..3 ---
    const int my_h = lane >> 2;    // head owning channels lane*8..lane*8+7
    float w0 = __shfl_sync(0xffffffffu, wgt, my_h);
    float w1 = __shfl_sync(0xffffffffu, wgt, 8 + my_h);
    float w2_ = __shfl_sync(0xffffffffu, wgt, 16 + my_h);
    float w3 = __shfl_sync(0xffffffffu, wgt, 24 + my_h);
    int o0 = __shfl_sync(0xffffffffu, wofs, 0);
    int o1 = __shfl_sync(0xffffffffu, wofs, 8);
    int o2 = __shfl_sync(0xffffffffu, wofs, 16);
    int o3 = __shfl_sync(0xffffffffu, wofs, 24);

    // --- fold: 8 channels per lane ---
    const float* vbase = KV + (uint32_t)b * (NWIN * KVD) + DIM + lane * 8;
    float4 oa = make_float4(0.f, 0.f, 0.f, 0.f);
    float4 ob = make_float4(0.f, 0.f, 0.f, 0.f);
#pragma unroll
    for (int s = 0; s < 4; s++) {
        const float wg = (s == 0) ? w0 : (s == 1) ? w1 : (s == 2) ? w2_ : w3;
        const int   of = (s == 0) ? o0 : (s == 1) ? o1 : (s == 2) ? o2 : o3;
        const float4 va = *(const float4*)(vbase + of);
        const float4 vb = *(const float4*)(vbase + of + 4);
        oa.x = fmaf(wg, va.x, oa.x); oa.y = fmaf(wg, va.y, oa.y);
        oa.z = fmaf(wg, va.z, oa.z); oa.w = fmaf(wg, va.w, oa.w);
        ob.x = fmaf(wg, vb.x, ob.x); ob.y = fmaf(wg, vb.y, ob.y);
        ob.z = fmaf(wg, vb.z, ob.z); ob.w = fmaf(wg, vb.w, ob.w);
    }

    float xs[8] = {oa.x, oa.y, oa.z, oa.w, ob.x, ob.y, ob.z, ob.w};
    unsigned short hb[8], lb[8];
#pragma unroll
    for (int k = 0; k < 8; k++) {
        __nv_bfloat16 hi = __float2bfloat16(xs[k]);
        __nv_bfloat16 lo = __float2bfloat16(xs[k] - __bfloat162float(hi));
        hb[k] = __bfloat16_as_ushort(hi);
        lb[k] = __bfloat16_as_ushort(lo);
    }
    const uint32_t idx = ((uint32_t)pix * DIM + lane * 8) / 4;
    ((ushort4*)Phi)[idx]     = make_ushort4(hb[0], hb[1], hb[2], hb[3]);
    ((ushort4*)Phi)[idx + 1] = make_ushort4(hb[4], hb[5], hb[6], hb[7]);
    ((ushort4*)Plo)[idx]     = make_ushort4(lb[0], lb[1], lb[2], lb[3]);
    ((ushort4*)Plo)[idx + 1] = make_ushort4(lb[4], lb[5], lb[6], lb[7]);
}

// ---------------------------------------------------------------------------
// Launch
// ---------------------------------------------------------------------------
extern "C" void kernel_launch(void* const* d_in, const int* in_sizes, int n_in,
                              void* d_out, int out_size)
{
    (void)in_sizes; (void)n_in; (void)out_size;
    const float* Xt       = (const float*)d_in[0];
    const float* Xb       = (const float*)d_in[1];
    const float* q_w      = (const float*)d_in[2];
    const float* kv_w     = (const float*)d_in[3];
    const float* proj_w   = (const float*)d_in[4];
    const float* proj_b   = (const float*)d_in[5];
    const float* rel_init = (const float*)d_in[6];
    const float* rel_bias = (const float*)d_in[7];
    float* out = (float*)d_out;

    float *Qb, *KVb;
    __nv_bfloat16 *Xbh, *Xbl, *Xth, *Xtl, *Ph, *Pl;
    __nv_bfloat16 *wqh, *wql, *wkh, *wkl, *wph, *wpl;
    cudaGetSymbolAddress((void**)&Qb,  g_Q);
    cudaGetSymbolAddress((void**)&KVb, g_KV);
    cudaGetSymbolAddress((void**)&Xbh, g_Xbh);
    cudaGetSymbolAddress((void**)&Xbl, g_Xbl);
    cudaGetSymbolAddress((void**)&Xth, g_Xth);
    cudaGetSymbolAddress((void**)&Xtl, g_Xtl);
    cudaGetSymbolAddress((void**)&Ph,  g_Ph);
    cudaGetSymbolAddress((void**)&Pl,  g_Pl);
    cudaGetSymbolAddress((void**)&wqh, g_wqh);
    cudaGetSymbolAddress((void**)&wql, g_wql);
    cudaGetSymbolAddress((void**)&wkh, g_wkh);
    cudaGetSymbolAddress((void**)&wkl, g_wkl);
    cudaGetSymbolAddress((void**)&wph, g_wph);
    cudaGetSymbolAddress((void**)&wpl, g_wpl);

    cudaFuncSetAttribute(gemm_qkv,
                         cudaFuncAttributeMaxDynamicSharedMemorySize, GEMM_SMEM);
    cudaFuncSetAttribute(gemm_proj,
                         cudaFuncAttributeMaxDynamicSharedMemorySize, GEMM_SMEM);

    // fused splits
    split_all<<<(S4 / 2 + 255) / 256, 256>>>(Xb, Xt, q_w, kv_w, proj_w,
                                             Xbh, Xbl, Xth, Xtl,
                                             wqh, wql, wkh, wkl, wph, wpl);

    // 1+2) KV = Xt @ kv_w^T (long tiles first) and Q = Xb @ q_w^T
    gemm_qkv<<<QBLKS + KVBLKS, 128, GEMM_SMEM>>>(
        Xbh, Xbl, wqh, wql, Xth, Xtl, wkh, wkl, Qb, KVb);

    // 3) attention numerators + sums (warp per pixel)
    attn_phase1<<<(BATCH * NPIX) / 8, 256>>>(Qb, KVb, rel_init, rel_bias);

    // 4) normalization + V + fold (warp per pixel, writes split P)
    attn_phase2<<<(BATCH * NPIX) / 8, 256>>>(KVb, Ph, Pl);

    // 5) Out = P @ proj_w^T + proj_b
    gemm_proj<<<dim3(DIM / TBN, (BATCH * NPIX) / TBM), 128, GEMM_SMEM>>>(
        Ph, Pl, wph, wpl, proj_b, out);
}